// round 8
// baseline (speedup 1.0000x reference)
#include <cuda_runtime.h>
#include <cuda_bf16.h>
#include <math.h>
#include <cstdint>

// ---------------- problem constants ----------------
#define Vn 32000
#define En 1024
#define Tn 2048
#define Hn 16
#define Dh 64
#define Ln 4
#define FFn 4096
#define Bn 4
#define ROWS (Bn * Tn)          // 8192
#define NHEADTOK (ROWS * Hn)    // 131072

// ---------------- scratch (static device memory) -------------------------
#define SZ_X   ((size_t)ROWS * En)
#define OFF_X  ((size_t)0)
#define OFF_Q  (OFF_X + SZ_X)
#define OFF_K  (OFF_Q + SZ_X)
#define OFF_V  (OFF_K + SZ_X)
#define OFF_O  (OFF_V + SZ_X)
#define OFF_FF (OFF_O + SZ_X)                    // ROWS*FFn floats; reused as Vt during attention
#define OFF_S  (OFF_FF + (size_t)ROWS * FFn)
#define OFF_RL (OFF_S + (size_t)Bn * Hn * Tn * Tn)
#define TOTALF (OFF_RL + ROWS + 64)

__device__ float g_buf[TOTALF];
__device__ int   g_flags[2];

// =================== baseline-PTX helpers =================================
__device__ __forceinline__ uint32_t smem_u32(const void* p) {
    uint32_t a;
    asm("{ .reg .u64 t; cvta.to.shared.u64 t, %1; cvt.u32.u64 %0, t; }" : "=r"(a) : "l"(p));
    return a;
}
__device__ __forceinline__ uint32_t cvt1(float f) {
    uint32_t u;
    asm("cvt.rna.tf32.f32 %0, %1;" : "=r"(u) : "f"(f));
    return u;
}
__device__ __forceinline__ void cp16(uint32_t dst, const float* src) {
    asm volatile("cp.async.cg.shared.global [%0], [%1], 16;" :: "r"(dst), "l"(src));
}
#define CP_COMMIT() asm volatile("cp.async.commit_group;" ::: "memory")

__device__ __forceinline__ void mma8(float c[4], const uint32_t a[4], const uint32_t b[2]) {
    asm volatile(
        "mma.sync.aligned.m16n8k8.row.col.f32.tf32.tf32.f32 "
        "{%0,%1,%2,%3}, {%4,%5,%6,%7}, {%8,%9}, {%0,%1,%2,%3};"
        : "+f"(c[0]), "+f"(c[1]), "+f"(c[2]), "+f"(c[3])
        : "r"(a[0]), "r"(a[1]), "r"(a[2]), "r"(a[3]), "r"(b[0]), "r"(b[1]));
}

// =================== warp-mma tf32 NT GEMM (cp.async 4-stage) =============
// C[M,N] = alpha*(A[M,K] @ B[N,K]^T) + bias, optional exact GELU.
// BM=128, BN in {64,128}, BK=16, 8 warps (4x2). Batched over z=z1*z2dim+z2.
// CAUSAL: 0 none, 1 skip tiles with n0>m0 (scores), 2 cap K at m0+128 (A*V).
template<int BN, int CAUSAL>
__global__ void __launch_bounds__(256)
mma_nt(const float* __restrict__ A, const float* __restrict__ B,
       const float* __restrict__ bias, float* __restrict__ C,
       int K, int lda, int ldb, int ldc,
       int z2dim,
       long long sA1, long long sA2, long long sB1, long long sB2,
       long long sC1, long long sC2,
       float alpha, int fuse_gelu)
{
    constexpr int BM = 128, BK = 16, SP = 20, STAGES = 4;
    constexpr int WN = BN / 2;                 // warp n-extent (4x2 warp grid)
    constexpr int NT = WN / 8;                 // n8 tiles per warp
    constexpr int NB = BN / 64;                // B 16B-chunk loads per thread
    constexpr int STG = (BM + BN) * SP;        // floats per stage

    const int m0 = blockIdx.x * BM;
    const int n0 = blockIdx.y * BN;
    if (CAUSAL == 1 && n0 > m0) return;

    {
        int bz = blockIdx.z;
        int z1 = bz / z2dim, z2 = bz - z1 * z2dim;
        A += z1 * sA1 + z2 * sA2;
        B += z1 * sB1 + z2 * sB2;
        C += z1 * sC1 + z2 * sC2;
    }
    const int Keff = (CAUSAL == 2) ? min(K, m0 + BM) : K;

    extern __shared__ float sm[];
    const uint32_t sbase = smem_u32(sm);

    const int tid = threadIdx.x;
    const int wid = tid >> 5, lane = tid & 31;
    const int wm = wid & 3, wn = wid >> 2;     // warp coords in 4x2
    const int grp = lane >> 2, tig = lane & 3;

    float acc[2][NT][4];
#pragma unroll
    for (int mt = 0; mt < 2; mt++)
#pragma unroll
        for (int nt = 0; nt < NT; nt++)
#pragma unroll
            for (int j = 0; j < 4; j++) acc[mt][nt][j] = 0.f;

    // ---- issue cp.async for one BK tile into stage st ----
    auto load = [&](int st, int kt) {
        const int k0 = kt * BK;
        uint32_t abase = sbase + (uint32_t)st * STG * 4;
        uint32_t bbase = abase + BM * SP * 4;
#pragma unroll
        for (int i = 0; i < 2; i++) {          // A: 128 rows x 4 chunks
            int c = tid + i * 256;
            int r = c >> 2, c4 = (c & 3) * 4;
            cp16(abase + (r * SP + c4) * 4, A + (long long)(m0 + r) * lda + k0 + c4);
        }
#pragma unroll
        for (int i = 0; i < NB; i++) {         // B: BN rows x 4 chunks
            int c = tid + i * 256;
            int r = c >> 2, c4 = (c & 3) * 4;
            cp16(bbase + (r * SP + c4) * 4, B + (long long)(n0 + r) * ldb + k0 + c4);
        }
    };

    // ---- compute one BK tile from stage st (cvt.rna at fragment load) ----
    auto compute = [&](int st) {
        const float* Af = sm + (size_t)st * STG;
        const float* Bf = Af + BM * SP;
#pragma unroll
        for (int ks = 0; ks < 2; ks++) {
            const int kb = ks * 8;
            uint32_t af[2][4];
#pragma unroll
            for (int mt = 0; mt < 2; mt++) {
                int row = wm * 32 + mt * 16;
                af[mt][0] = cvt1(Af[(row + grp) * SP + kb + tig]);
                af[mt][1] = cvt1(Af[(row + grp + 8) * SP + kb + tig]);
                af[mt][2] = cvt1(Af[(row + grp) * SP + kb + tig + 4]);
                af[mt][3] = cvt1(Af[(row + grp + 8) * SP + kb + tig + 4]);
            }
            uint32_t bf[NT][2];
#pragma unroll
            for (int nt = 0; nt < NT; nt++) {
                int col = wn * WN + nt * 8 + grp;
                bf[nt][0] = cvt1(Bf[col * SP + kb + tig]);
                bf[nt][1] = cvt1(Bf[col * SP + kb + tig + 4]);
            }
#pragma unroll
            for (int mt = 0; mt < 2; mt++)
#pragma unroll
                for (int nt = 0; nt < NT; nt++)
                    mma8(acc[mt][nt], af[mt], bf[nt]);
        }
    };

    const int nkt = Keff / BK;
#pragma unroll
    for (int s = 0; s < STAGES - 1; s++) {     // prologue
        if (s < nkt) load(s, s);
        CP_COMMIT();
    }
    for (int kt = 0; kt < nkt; kt++) {
        asm volatile("cp.async.wait_group %0;" :: "n"(STAGES - 2) : "memory");
        __syncthreads();
        const int nk = kt + STAGES - 1;
        if (nk < nkt) load(nk % STAGES, nk);
        CP_COMMIT();
        compute(kt % STAGES);
    }

    // ---- epilogue ----
#pragma unroll
    for (int mt = 0; mt < 2; mt++) {
#pragma unroll
        for (int nt = 0; nt < NT; nt++) {
            const int col = n0 + wn * WN + nt * 8 + tig * 2;
            float b0 = bias ? bias[col] : 0.f;
            float b1 = bias ? bias[col + 1] : 0.f;
#pragma unroll
            for (int h = 0; h < 2; h++) {
                const long long row = m0 + wm * 32 + mt * 16 + grp + h * 8;
                float v0 = acc[mt][nt][h * 2 + 0] * alpha + b0;
                float v1 = acc[mt][nt][h * 2 + 1] * alpha + b1;
                if (fuse_gelu) {
                    v0 = 0.5f * v0 * (1.0f + erff(v0 * 0.70710678118654752f));
                    v1 = 0.5f * v1 * (1.0f + erff(v1 * 0.70710678118654752f));
                }
                *(float2*)(C + row * ldc + col) = make_float2(v0, v1);
            }
        }
    }
}

#define SMEM_GEMM(BN) (4 * (128 + (BN)) * 20 * 4)

// =================== dtype detect / embed / LN / softmax / loss ===========
__global__ void detect_kernel(const void* idxp) {
    __shared__ int bad;
    if (threadIdx.x == 0) bad = 0;
    __syncthreads();
    const long long* p = (const long long*)idxp;
    for (int i = threadIdx.x; i < ROWS / 2; i += blockDim.x) {
        long long v = p[i];
        if (v < 0 || v >= Vn) bad = 1;
    }
    __syncthreads();
    if (threadIdx.x == 0) g_flags[0] = bad ? 0 : 1;
}

__device__ __forceinline__ long long read_token(const void* p, int i) {
    if (g_flags[0]) return ((const long long*)p)[i];
    return (long long)((const int*)p)[i];
}

__global__ void embed_kernel(const void* idxp, const float* __restrict__ tok,
                             const float* __restrict__ pos, float* __restrict__ x) {
    int row = blockIdx.x;
    int t = row % Tn;
    long long token = read_token(idxp, row);
    const float* te = tok + (size_t)token * En;
    const float* pe = pos + (size_t)t * En;
    float* xo = x + (size_t)row * En;
#pragma unroll
    for (int i = 0; i < En / 256; i++) {
        int c = threadIdx.x + i * 256;
        xo[c] = te[c] + pe[c];
    }
}

// V [B,T,H,Dh] -> Vt [B,H,Dh,T]
__global__ void transpose_v(const float* __restrict__ V, float* __restrict__ Vt) {
    __shared__ float tile[32][33];
    int bh = blockIdx.z;
    int b = bh / Hn, h = bh - b * Hn;
    int t0 = blockIdx.x * 32, d0 = blockIdx.y * 32;
    int tx = threadIdx.x, ty0 = threadIdx.y;
#pragma unroll
    for (int i = 0; i < 4; i++) {
        int ty = ty0 + i * 8;
        tile[ty][tx] = V[((size_t)(b * Tn + t0 + ty) * Hn + h) * Dh + d0 + tx];
    }
    __syncthreads();
#pragma unroll
    for (int i = 0; i < 4; i++) {
        int ty = ty0 + i * 8;
        Vt[((size_t)(b * Hn + h) * Dh + d0 + ty) * Tn + t0 + tx] = tile[tx][ty];
    }
}

__global__ void softmax_causal(float* __restrict__ S) {
    long long row = blockIdx.x;
    int i = (int)(row % Tn);
    float* p = S + row * (long long)Tn;
    int n = i + 1;
    int jend = (i & ~127) + 128;         // A*V never reads past this row-tile's K cap
    int tid = threadIdx.x;
    __shared__ float red[256];

    float mx = -1e30f;
    for (int j = tid; j < n; j += 256) mx = fmaxf(mx, p[j]);
    red[tid] = mx; __syncthreads();
    for (int s = 128; s > 0; s >>= 1) { if (tid < s) red[tid] = fmaxf(red[tid], red[tid + s]); __syncthreads(); }
    mx = red[0]; __syncthreads();

    float sum = 0.f;
    for (int j = tid; j < n; j += 256) sum += expf(p[j] - mx);
    red[tid] = sum; __syncthreads();
    for (int s = 128; s > 0; s >>= 1) { if (tid < s) red[tid] += red[tid + s]; __syncthreads(); }
    float inv = 1.0f / red[0];

    for (int j = tid; j < n; j += 256) p[j] = expf(p[j] - mx) * inv;
    for (int j = n + tid; j < jend; j += 256) p[j] = 0.f;
}

__global__ void add_layernorm(const float* __restrict__ a, const float* __restrict__ res,
                              const float* __restrict__ g, const float* __restrict__ b,
                              float* __restrict__ out)
{
    int row = blockIdx.x;
    const float* pa = a + (size_t)row * En;
    const float* pr = res ? res + (size_t)row * En : nullptr;
    float* po = out + (size_t)row * En;
    int tid = threadIdx.x;
    __shared__ float red[256];
    float v[En / 256];

    float s = 0.f;
#pragma unroll
    for (int i = 0; i < En / 256; i++) {
        int c = tid + i * 256;
        float x = pa[c] + (pr ? pr[c] : 0.f);
        v[i] = x; s += x;
    }
    red[tid] = s; __syncthreads();
    for (int st = 128; st > 0; st >>= 1) { if (tid < st) red[tid] += red[tid + st]; __syncthreads(); }
    float mean = red[0] * (1.0f / En); __syncthreads();

    float s2 = 0.f;
#pragma unroll
    for (int i = 0; i < En / 256; i++) { float d = v[i] - mean; s2 += d * d; }
    red[tid] = s2; __syncthreads();
    for (int st = 128; st > 0; st >>= 1) { if (tid < st) red[tid] += red[tid + st]; __syncthreads(); }
    float inv = rsqrtf(red[0] * (1.0f / En) + 1e-5f);

#pragma unroll
    for (int i = 0; i < En / 256; i++) {
        int c = tid + i * 256;
        po[c] = (v[i] - mean) * inv * g[c] + b[c];
    }
}

__global__ void loss_rows(const float* __restrict__ logits, const void* tgt,
                          float* __restrict__ rowloss)
{
    int r = blockIdx.x;
    const float* p = logits + (size_t)r * Vn;
    int tid = threadIdx.x;
    __shared__ float red[256];

    float mx = -1e30f;
    for (int j = tid; j < Vn; j += 256) mx = fmaxf(mx, p[j]);
    red[tid] = mx; __syncthreads();
    for (int s = 128; s > 0; s >>= 1) { if (tid < s) red[tid] = fmaxf(red[tid], red[tid + s]); __syncthreads(); }
    mx = red[0]; __syncthreads();

    float sum = 0.f;
    for (int j = tid; j < Vn; j += 256) sum += expf(p[j] - mx);
    red[tid] = sum; __syncthreads();
    for (int s = 128; s > 0; s >>= 1) { if (tid < s) red[tid] += red[tid + s]; __syncthreads(); }

    if (tid == 0) {
        long long t = read_token(tgt, r);
        rowloss[r] = logf(red[0]) + mx - p[t];
    }
}

__global__ void loss_reduce(const float* __restrict__ rowloss, float* __restrict__ out) {
    __shared__ float red[256];
    int tid = threadIdx.x;
    float s = 0.f;
    for (int i = tid; i < ROWS; i += 256) s += rowloss[i];
    red[tid] = s; __syncthreads();
    for (int st = 128; st > 0; st >>= 1) { if (tid < st) red[tid] += red[tid + st]; __syncthreads(); }
    if (tid == 0) out[0] = red[0] * (1.0f / ROWS);
}

// =================== host orchestration ===================================
extern "C" void kernel_launch(void* const* d_in, const int* in_sizes, int n_in,
                              void* d_out, int out_size)
{
    const void*  idx     = d_in[0];
    const void*  tgt     = d_in[1];
    const float* tok_emb = (const float*)d_in[2];
    const float* pos_emb = (const float*)d_in[3];
    const float* Wq      = (const float*)d_in[4];
    const float* Wk      = (const float*)d_in[5];
    const float* Wv      = (const float*)d_in[6];
    const float* Wo      = (const float*)d_in[7];
    const float* bo      = (const float*)d_in[8];
    const float* ln1_g   = (const float*)d_in[9];
    const float* ln1_b   = (const float*)d_in[10];
    const float* W1      = (const float*)d_in[11];
    const float* b1      = (const float*)d_in[12];
    const float* W2      = (const float*)d_in[13];
    const float* b2      = (const float*)d_in[14];
    const float* ln2_g   = (const float*)d_in[15];
    const float* ln2_b   = (const float*)d_in[16];
    const float* lnf_g   = (const float*)d_in[17];
    const float* lnf_b   = (const float*)d_in[18];
    const float* lm_w    = (const float*)d_in[19];
    const float* lm_b    = (const float*)d_in[20];

    cudaFuncSetAttribute(mma_nt<128, 0>, cudaFuncAttributeMaxDynamicSharedMemorySize, SMEM_GEMM(128));
    cudaFuncSetAttribute(mma_nt<128, 1>, cudaFuncAttributeMaxDynamicSharedMemorySize, SMEM_GEMM(128));
    cudaFuncSetAttribute(mma_nt<64, 0>,  cudaFuncAttributeMaxDynamicSharedMemorySize, SMEM_GEMM(64));
    cudaFuncSetAttribute(mma_nt<64, 2>,  cudaFuncAttributeMaxDynamicSharedMemorySize, SMEM_GEMM(64));

    float* buf = nullptr;
    cudaGetSymbolAddress((void**)&buf, g_buf);
    float* X  = buf + OFF_X;
    float* Q  = buf + OFF_Q;
    float* Kb = buf + OFF_K;
    float* Vb = buf + OFF_V;
    float* O  = buf + OFF_O;
    float* FF = buf + OFF_FF;     // also Vt scratch during attention
    float* Vt = FF;
    float* S  = buf + OFF_S;
    float* RL = buf + OFF_RL;

    const size_t NLOG = (size_t)ROWS * Vn;
    float* logits;
    long long loss_idx;
    if ((size_t)out_size >= NLOG + 1) { logits = (float*)d_out; loss_idx = (long long)NLOG; }
    else if ((size_t)out_size == NLOG) { logits = (float*)d_out; loss_idx = -1; }
    else { logits = S; loss_idx = 0; }

    detect_kernel<<<1, 256>>>(idx);
    embed_kernel<<<ROWS, 256>>>(idx, tok_emb, pos_emb, X);

    const long long TnE  = (long long)Tn * En;
    const long long TnTn = (long long)Tn * Tn;

    for (int l = 0; l < Ln; l++) {
        const float* wq = Wq + (size_t)l * Dh * Dh;
        const float* wk = Wk + (size_t)l * Dh * Dh;
        const float* wv = Wv + (size_t)l * Dh * Dh;
        const float* wo = Wo + (size_t)l * En * En;
        const float* w1 = W1 + (size_t)l * FFn * En;
        const float* w2 = W2 + (size_t)l * En * FFn;

        // q/k/v : [NHEADTOK,64] @ [64,64]^T
        dim3 gp(NHEADTOK / 128, 1, 1);
        mma_nt<64, 0><<<gp, 256, SMEM_GEMM(64)>>>(X, wq, nullptr, Q,  Dh, Dh, Dh, Dh,
                                                  1, 0, 0, 0, 0, 0, 0, 1.0f, 0);
        mma_nt<64, 0><<<gp, 256, SMEM_GEMM(64)>>>(X, wk, nullptr, Kb, Dh, Dh, Dh, Dh,
                                                  1, 0, 0, 0, 0, 0, 0, 1.0f, 0);
        mma_nt<64, 0><<<gp, 256, SMEM_GEMM(64)>>>(X, wv, nullptr, Vb, Dh, Dh, Dh, Dh,
                                                  1, 0, 0, 0, 0, 0, 0, 1.0f, 0);
        transpose_v<<<dim3(Tn / 32, 2, Bn * Hn), dim3(32, 8)>>>(Vb, Vt);

        // scores = Q K^T / 8  (lower+diag tiles only)
        mma_nt<128, 1><<<dim3(Tn / 128, Tn / 128, Bn * Hn), 256, SMEM_GEMM(128)>>>(
            Q, Kb, nullptr, S, Dh, En, En, Tn,
            Hn, TnE, (long long)Dh, TnE, (long long)Dh,
            (long long)Hn * TnTn, TnTn, 0.125f, 0);

        softmax_causal<<<Bn * Hn * Tn, 256>>>(S);

        // O = S @ V = S @ Vt^T  (K capped causally per row tile)
        mma_nt<64, 2><<<dim3(Tn / 128, 1, Bn * Hn), 256, SMEM_GEMM(64)>>>(
            S, Vt, nullptr, O, Tn, Tn, Tn, En,
            Hn, (long long)Hn * TnTn, TnTn,
            (long long)Hn * Dh * Tn, (long long)Dh * Tn,
            TnE, (long long)Dh, 1.0f, 0);

        // attn proj
        mma_nt<128, 0><<<dim3(ROWS / 128, En / 128, 1), 256, SMEM_GEMM(128)>>>(
            O, wo, bo + (size_t)l * En, Q, En, En, En, En,
            1, 0, 0, 0, 0, 0, 0, 1.0f, 0);
        add_layernorm<<<ROWS, 256>>>(Q, X, ln1_g + (size_t)l * En, ln1_b + (size_t)l * En, X);

        // FFN
        mma_nt<128, 0><<<dim3(ROWS / 128, FFn / 128, 1), 256, SMEM_GEMM(128)>>>(
            X, w1, b1 + (size_t)l * FFn, FF, En, En, En, FFn,
            1, 0, 0, 0, 0, 0, 0, 1.0f, 1);   // fused exact GELU
        mma_nt<128, 0><<<dim3(ROWS / 128, En / 128, 1), 256, SMEM_GEMM(128)>>>(
            FF, w2, b2 + (size_t)l * En, Q, FFn, FFn, FFn, En,
            1, 0, 0, 0, 0, 0, 0, 1.0f, 0);
        add_layernorm<<<ROWS, 256>>>(Q, X, ln2_g + (size_t)l * En, ln2_b + (size_t)l * En, X);
    }

    add_layernorm<<<ROWS, 256>>>(X, nullptr, lnf_g, lnf_b, X);

    // LM head
    mma_nt<128, 0><<<dim3(ROWS / 128, Vn / 128, 1), 256, SMEM_GEMM(128)>>>(
        X, lm_w, lm_b, logits, En, En, En, Vn,
        1, 0, 0, 0, 0, 0, 0, 1.0f, 0);

    loss_rows<<<ROWS, 256>>>(logits, tgt, RL);
    if (loss_idx >= 0)
        loss_reduce<<<1, 256>>>(RL, ((float*)d_out) + loss_idx);
}

// round 11
// speedup vs baseline: 1.6389x; 1.6389x over previous
#include <cuda_runtime.h>
#include <cuda_bf16.h>
#include <math.h>
#include <cstdint>

// ---------------- problem constants ----------------
#define Vn 32000
#define En 1024
#define Tn 2048
#define Hn 16
#define Dh 64
#define Ln 4
#define FFn 4096
#define Bn 4
#define ROWS (Bn * Tn)          // 8192
#define NHEADTOK (ROWS * Hn)    // 131072

// ---------------- scratch (static device memory) -------------------------
#define SZ_X   ((size_t)ROWS * En)
#define OFF_X  ((size_t)0)
#define OFF_Q  (OFF_X + SZ_X)
#define OFF_K  (OFF_Q + SZ_X)
#define OFF_V  (OFF_K + SZ_X)
#define OFF_O  (OFF_V + SZ_X)
#define OFF_FF (OFF_O + SZ_X)                    // ROWS*FFn floats; reused as Vt during attention
#define OFF_S  (OFF_FF + (size_t)ROWS * FFn)
#define OFF_RL (OFF_S + (size_t)Bn * Hn * Tn * Tn)
#define TOTALF (OFF_RL + ROWS + 64)

__device__ float g_buf[TOTALF];
__device__ int   g_flags[2];

// =================== helpers (all proven on-HW in R7/R8) ==================
__device__ __forceinline__ uint4 tf32x4(float4 v) {
    uint4 w;
    asm("cvt.rna.tf32.f32 %0, %1;" : "=r"(w.x) : "f"(v.x));
    asm("cvt.rna.tf32.f32 %0, %1;" : "=r"(w.y) : "f"(v.y));
    asm("cvt.rna.tf32.f32 %0, %1;" : "=r"(w.z) : "f"(v.z));
    asm("cvt.rna.tf32.f32 %0, %1;" : "=r"(w.w) : "f"(v.w));
    return w;
}
__device__ __forceinline__ void mma8(float c[4], const uint32_t a[4], const uint32_t b[2]) {
    asm volatile(
        "mma.sync.aligned.m16n8k8.row.col.f32.tf32.tf32.f32 "
        "{%0,%1,%2,%3}, {%4,%5,%6,%7}, {%8,%9}, {%0,%1,%2,%3};"
        : "+f"(c[0]), "+f"(c[1]), "+f"(c[2]), "+f"(c[3])
        : "r"(a[0]), "r"(a[1]), "r"(a[2]), "r"(a[3]), "r"(b[0]), "r"(b[1]));
}

// =================== warp-mma tf32 NT GEMM (BK=32, reg-staged) ============
// C[M,N] = alpha*(A[M,K] @ B[N,K]^T) + bias, optional exact GELU.
// BM=128, BN in {64,128}, BK=32, 8 warps (4x2). Batched over z=z1*z2dim+z2.
// CAUSAL: 0 none, 1 skip tiles n0>m0 (scores), 2 cap K at m0+128 (A*V).
template<int BN, int CAUSAL>
__global__ void __launch_bounds__(256)
mma_nt(const float* __restrict__ A, const float* __restrict__ B,
       const float* __restrict__ bias, float* __restrict__ C,
       int K, int lda, int ldb, int ldc,
       int z2dim,
       long long sA1, long long sA2, long long sB1, long long sB2,
       long long sC1, long long sC2,
       float alpha, int fuse_gelu)
{
    constexpr int BM = 128, BK = 32, SP = BK + 4;   // padded stride (floats)
    constexpr int WN = BN / 2;                      // warp n-extent (4x2 warps)
    constexpr int NT = WN / 8;                      // n8 tiles per warp
    constexpr int NB = BN / 32;                     // B float4 loads per thread

    const int m0 = blockIdx.x * BM;
    const int n0 = blockIdx.y * BN;
    if (CAUSAL == 1 && n0 > m0) return;

    {
        int bz = blockIdx.z;
        int z1 = bz / z2dim, z2 = bz - z1 * z2dim;
        A += z1 * sA1 + z2 * sA2;
        B += z1 * sB1 + z2 * sB2;
        C += z1 * sC1 + z2 * sC2;
    }
    const int Keff = (CAUSAL == 2) ? min(K, m0 + BM) : K;

    extern __shared__ float sm[];
    float* As0 = sm;                               // [2][BM*SP]
    float* Bs0 = sm + 2 * BM * SP;                 // [2][BN*SP]

    const int tid = threadIdx.x;
    const int wid = tid >> 5, lane = tid & 31;
    const int wm = wid & 3, wn = wid >> 2;
    const int grp = lane >> 2, tig = lane & 3;

    float acc[2][NT][4];
#pragma unroll
    for (int mt = 0; mt < 2; mt++)
#pragma unroll
        for (int nt = 0; nt < NT; nt++)
#pragma unroll
            for (int j = 0; j < 4; j++) acc[mt][nt][j] = 0.f;

    float4 aR[4], bR[NB];

    auto load_tile = [&](int kt) {
        const int k0 = kt * BK;
#pragma unroll
        for (int i = 0; i < 4; i++) {              // A: 128 rows x 8 chunks
            int f = tid + i * 256;
            int r = f >> 3, c4 = (f & 7) * 4;
            aR[i] = *(const float4*)(A + (long long)(m0 + r) * lda + k0 + c4);
        }
#pragma unroll
        for (int i = 0; i < NB; i++) {             // B: BN rows x 8 chunks
            int f = tid + i * 256;
            int r = f >> 3, c4 = (f & 7) * 4;
            bR[i] = *(const float4*)(B + (long long)(n0 + r) * ldb + k0 + c4);
        }
    };
    auto store_tile = [&](int s) {
        float* As = As0 + s * BM * SP;
        float* Bs = Bs0 + s * BN * SP;
#pragma unroll
        for (int i = 0; i < 4; i++) {
            int f = tid + i * 256;
            int r = f >> 3, c4 = (f & 7) * 4;
            *(uint4*)&As[r * SP + c4] = tf32x4(aR[i]);
        }
#pragma unroll
        for (int i = 0; i < NB; i++) {
            int f = tid + i * 256;
            int r = f >> 3, c4 = (f & 7) * 4;
            *(uint4*)&Bs[r * SP + c4] = tf32x4(bR[i]);
        }
    };
    auto compute = [&](int s) {
        const uint32_t* Au = (const uint32_t*)(As0 + s * BM * SP);
        const uint32_t* Bu = (const uint32_t*)(Bs0 + s * BN * SP);
#pragma unroll
        for (int ks = 0; ks < 4; ks++) {
            const int kb = ks * 8;
            uint32_t af[2][4];
#pragma unroll
            for (int mt = 0; mt < 2; mt++) {
                int row = wm * 32 + mt * 16;
                af[mt][0] = Au[(row + grp) * SP + kb + tig];
                af[mt][1] = Au[(row + grp + 8) * SP + kb + tig];
                af[mt][2] = Au[(row + grp) * SP + kb + tig + 4];
                af[mt][3] = Au[(row + grp + 8) * SP + kb + tig + 4];
            }
            uint32_t bf[NT][2];
#pragma unroll
            for (int nt = 0; nt < NT; nt++) {
                int col = wn * WN + nt * 8 + grp;
                bf[nt][0] = Bu[col * SP + kb + tig];
                bf[nt][1] = Bu[col * SP + kb + tig + 4];
            }
#pragma unroll
            for (int mt = 0; mt < 2; mt++)
#pragma unroll
                for (int nt = 0; nt < NT; nt++)
                    mma8(acc[mt][nt], af[mt], bf[nt]);
        }
    };

    const int nkt = Keff / BK;
    load_tile(0);
    store_tile(0);
    __syncthreads();
    for (int kt = 0; kt < nkt; kt++) {
        const int s = kt & 1;
        if (kt + 1 < nkt) load_tile(kt + 1);
        compute(s);
        if (kt + 1 < nkt) { store_tile(s ^ 1); __syncthreads(); }
    }

    // ---- epilogue ----
#pragma unroll
    for (int mt = 0; mt < 2; mt++) {
#pragma unroll
        for (int nt = 0; nt < NT; nt++) {
            const int col = n0 + wn * WN + nt * 8 + tig * 2;
            float b0 = bias ? bias[col] : 0.f;
            float b1 = bias ? bias[col + 1] : 0.f;
#pragma unroll
            for (int h = 0; h < 2; h++) {
                const long long row = m0 + wm * 32 + mt * 16 + grp + h * 8;
                float v0 = acc[mt][nt][h * 2 + 0] * alpha + b0;
                float v1 = acc[mt][nt][h * 2 + 1] * alpha + b1;
                if (fuse_gelu) {
                    v0 = 0.5f * v0 * (1.0f + erff(v0 * 0.70710678118654752f));
                    v1 = 0.5f * v1 * (1.0f + erff(v1 * 0.70710678118654752f));
                }
                *(float2*)(C + row * ldc + col) = make_float2(v0, v1);
            }
        }
    }
}

#define SMEM_G(BN) (2 * (128 + (BN)) * 36 * 4)

// =================== small kernels ========================================
__global__ void detect_kernel(const void* idxp) {
    __shared__ int bad;
    if (threadIdx.x == 0) bad = 0;
    __syncthreads();
    const long long* p = (const long long*)idxp;
    for (int i = threadIdx.x; i < ROWS / 2; i += blockDim.x) {
        long long v = p[i];
        if (v < 0 || v >= Vn) bad = 1;
    }
    __syncthreads();
    if (threadIdx.x == 0) g_flags[0] = bad ? 0 : 1;
}

__device__ __forceinline__ long long read_token(const void* p, int i) {
    if (g_flags[0]) return ((const long long*)p)[i];
    return (long long)((const int*)p)[i];
}

__global__ void embed_kernel(const void* idxp, const float* __restrict__ tok,
                             const float* __restrict__ pos, float* __restrict__ x) {
    int row = blockIdx.x;
    int t = row % Tn;
    long long token = read_token(idxp, row);
    const float* te = tok + (size_t)token * En;
    const float* pe = pos + (size_t)t * En;
    float* xo = x + (size_t)row * En;
#pragma unroll
    for (int i = 0; i < En / 256; i++) {
        int c = threadIdx.x + i * 256;
        xo[c] = te[c] + pe[c];
    }
}

// V [B,T,H,Dh] -> Vt [B,H,Dh,T]
__global__ void transpose_v(const float* __restrict__ V, float* __restrict__ Vt) {
    __shared__ float tile[32][33];
    int bh = blockIdx.z;
    int b = bh / Hn, h = bh - b * Hn;
    int t0 = blockIdx.x * 32, d0 = blockIdx.y * 32;
    int tx = threadIdx.x, ty0 = threadIdx.y;
#pragma unroll
    for (int i = 0; i < 4; i++) {
        int ty = ty0 + i * 8;
        tile[ty][tx] = V[((size_t)(b * Tn + t0 + ty) * Hn + h) * Dh + d0 + tx];
    }
    __syncthreads();
#pragma unroll
    for (int i = 0; i < 4; i++) {
        int ty = ty0 + i * 8;
        Vt[((size_t)(b * Hn + h) * Dh + d0 + ty) * Tn + t0 + tx] = tile[tx][ty];
    }
}

// causal softmax, zero-fill trimmed to the 128-row tile cap (proven in R8)
__global__ void softmax_causal(float* __restrict__ S) {
    long long row = blockIdx.x;
    int i = (int)(row % Tn);
    float* p = S + row * (long long)Tn;
    int n = i + 1;
    int jend = (i & ~127) + 128;         // A*V never reads past this row-tile's K cap
    int tid = threadIdx.x;
    __shared__ float red[256];

    float mx = -1e30f;
    for (int j = tid; j < n; j += 256) mx = fmaxf(mx, p[j]);
    red[tid] = mx; __syncthreads();
    for (int s = 128; s > 0; s >>= 1) { if (tid < s) red[tid] = fmaxf(red[tid], red[tid + s]); __syncthreads(); }
    mx = red[0]; __syncthreads();

    float sum = 0.f;
    for (int j = tid; j < n; j += 256) sum += expf(p[j] - mx);
    red[tid] = sum; __syncthreads();
    for (int s = 128; s > 0; s >>= 1) { if (tid < s) red[tid] += red[tid + s]; __syncthreads(); }
    float inv = 1.0f / red[0];

    for (int j = tid; j < n; j += 256) p[j] = expf(p[j] - mx) * inv;
    for (int j = n + tid; j < jend; j += 256) p[j] = 0.f;
}

__global__ void add_layernorm(const float* __restrict__ a, const float* __restrict__ res,
                              const float* __restrict__ g, const float* __restrict__ b,
                              float* __restrict__ out)
{
    int row = blockIdx.x;
    const float* pa = a + (size_t)row * En;
    const float* pr = res ? res + (size_t)row * En : nullptr;
    float* po = out + (size_t)row * En;
    int tid = threadIdx.x;
    __shared__ float red[256];
    float v[En / 256];

    float s = 0.f;
#pragma unroll
    for (int i = 0; i < En / 256; i++) {
        int c = tid + i * 256;
        float x = pa[c] + (pr ? pr[c] : 0.f);
        v[i] = x; s += x;
    }
    red[tid] = s; __syncthreads();
    for (int st = 128; st > 0; st >>= 1) { if (tid < st) red[tid] += red[tid + st]; __syncthreads(); }
    float mean = red[0] * (1.0f / En); __syncthreads();

    float s2 = 0.f;
#pragma unroll
    for (int i = 0; i < En / 256; i++) { float d = v[i] - mean; s2 += d * d; }
    red[tid] = s2; __syncthreads();
    for (int st = 128; st > 0; st >>= 1) { if (tid < st) red[tid] += red[tid + st]; __syncthreads(); }
    float inv = rsqrtf(red[0] * (1.0f / En) + 1e-5f);

#pragma unroll
    for (int i = 0; i < En / 256; i++) {
        int c = tid + i * 256;
        po[c] = (v[i] - mean) * inv * g[c] + b[c];
    }
}

// single-pass online logsumexp loss per row
__global__ void loss_rows(const float* __restrict__ logits, const void* tgt,
                          float* __restrict__ rowloss)
{
    int r = blockIdx.x;
    const float* p = logits + (size_t)r * Vn;
    int tid = threadIdx.x;
    __shared__ float rm[256], rs[256];

    float m = -1e30f, s = 0.f;
    for (int j = tid; j < Vn; j += 256) {
        float x = p[j];
        if (x > m) { s = s * expf(m - x) + 1.f; m = x; }
        else s += expf(x - m);
    }
    rm[tid] = m; rs[tid] = s; __syncthreads();
    for (int st = 128; st > 0; st >>= 1) {
        if (tid < st) {
            float m2 = rm[tid + st], s2 = rs[tid + st];
            float M = fmaxf(rm[tid], m2);
            rs[tid] = rs[tid] * expf(rm[tid] - M) + s2 * expf(m2 - M);
            rm[tid] = M;
        }
        __syncthreads();
    }
    if (tid == 0) {
        long long t = read_token(tgt, r);
        rowloss[r] = logf(rs[0]) + rm[0] - p[t];
    }
}

__global__ void loss_reduce(const float* __restrict__ rowloss, float* __restrict__ out) {
    __shared__ float red[256];
    int tid = threadIdx.x;
    float s = 0.f;
    for (int i = tid; i < ROWS; i += 256) s += rowloss[i];
    red[tid] = s; __syncthreads();
    for (int st = 128; st > 0; st >>= 1) { if (tid < st) red[tid] += red[tid + st]; __syncthreads(); }
    if (tid == 0) out[0] = red[0] * (1.0f / ROWS);
}

// =================== host orchestration ===================================
extern "C" void kernel_launch(void* const* d_in, const int* in_sizes, int n_in,
                              void* d_out, int out_size)
{
    const void*  idx     = d_in[0];
    const void*  tgt     = d_in[1];
    const float* tok_emb = (const float*)d_in[2];
    const float* pos_emb = (const float*)d_in[3];
    const float* Wq      = (const float*)d_in[4];
    const float* Wk      = (const float*)d_in[5];
    const float* Wv      = (const float*)d_in[6];
    const float* Wo      = (const float*)d_in[7];
    const float* bo      = (const float*)d_in[8];
    const float* ln1_g   = (const float*)d_in[9];
    const float* ln1_b   = (const float*)d_in[10];
    const float* W1      = (const float*)d_in[11];
    const float* b1      = (const float*)d_in[12];
    const float* W2      = (const float*)d_in[13];
    const float* b2      = (const float*)d_in[14];
    const float* ln2_g   = (const float*)d_in[15];
    const float* ln2_b   = (const float*)d_in[16];
    const float* lnf_g   = (const float*)d_in[17];
    const float* lnf_b   = (const float*)d_in[18];
    const float* lm_w    = (const float*)d_in[19];
    const float* lm_b    = (const float*)d_in[20];

    cudaFuncSetAttribute(mma_nt<128, 0>, cudaFuncAttributeMaxDynamicSharedMemorySize, SMEM_G(128));
    cudaFuncSetAttribute(mma_nt<128, 1>, cudaFuncAttributeMaxDynamicSharedMemorySize, SMEM_G(128));
    cudaFuncSetAttribute(mma_nt<64, 0>,  cudaFuncAttributeMaxDynamicSharedMemorySize, SMEM_G(64));
    cudaFuncSetAttribute(mma_nt<64, 2>,  cudaFuncAttributeMaxDynamicSharedMemorySize, SMEM_G(64));

    float* buf = nullptr;
    cudaGetSymbolAddress((void**)&buf, g_buf);
    float* X  = buf + OFF_X;
    float* Q  = buf + OFF_Q;
    float* Kb = buf + OFF_K;
    float* Vb = buf + OFF_V;
    float* O  = buf + OFF_O;
    float* FF = buf + OFF_FF;     // also Vt scratch during attention
    float* Vt = FF;
    float* S  = buf + OFF_S;
    float* RL = buf + OFF_RL;

    const size_t NLOG = (size_t)ROWS * Vn;
    float* logits;
    long long loss_idx;
    if ((size_t)out_size >= NLOG + 1) { logits = (float*)d_out; loss_idx = (long long)NLOG; }
    else if ((size_t)out_size == NLOG) { logits = (float*)d_out; loss_idx = -1; }
    else { logits = S; loss_idx = 0; }

    detect_kernel<<<1, 256>>>(idx);
    embed_kernel<<<ROWS, 256>>>(idx, tok_emb, pos_emb, X);

    const long long TnE  = (long long)Tn * En;
    const long long TnTn = (long long)Tn * Tn;

    for (int l = 0; l < Ln; l++) {
        const float* wq = Wq + (size_t)l * Dh * Dh;
        const float* wk = Wk + (size_t)l * Dh * Dh;
        const float* wv = Wv + (size_t)l * Dh * Dh;
        const float* wo = Wo + (size_t)l * En * En;
        const float* w1 = W1 + (size_t)l * FFn * En;
        const float* w2 = W2 + (size_t)l * En * FFn;

        // q/k/v : [NHEADTOK,64] @ [64,64]^T
        dim3 gp(NHEADTOK / 128, 1, 1);
        mma_nt<64, 0><<<gp, 256, SMEM_G(64)>>>(X, wq, nullptr, Q,  Dh, Dh, Dh, Dh,
                                               1, 0, 0, 0, 0, 0, 0, 1.0f, 0);
        mma_nt<64, 0><<<gp, 256, SMEM_G(64)>>>(X, wk, nullptr, Kb, Dh, Dh, Dh, Dh,
                                               1, 0, 0, 0, 0, 0, 0, 1.0f, 0);
        mma_nt<64, 0><<<gp, 256, SMEM_G(64)>>>(X, wv, nullptr, Vb, Dh, Dh, Dh, Dh,
                                               1, 0, 0, 0, 0, 0, 0, 1.0f, 0);
        transpose_v<<<dim3(Tn / 32, 2, Bn * Hn), dim3(32, 8)>>>(Vb, Vt);

        // scores = Q K^T / 8  (lower+diag tiles only)
        mma_nt<128, 1><<<dim3(Tn / 128, Tn / 128, Bn * Hn), 256, SMEM_G(128)>>>(
            Q, Kb, nullptr, S, Dh, En, En, Tn,
            Hn, TnE, (long long)Dh, TnE, (long long)Dh,
            (long long)Hn * TnTn, TnTn, 0.125f, 0);

        softmax_causal<<<Bn * Hn * Tn, 256>>>(S);

        // O = S @ V = S @ Vt^T  (K capped causally per row tile)
        mma_nt<64, 2><<<dim3(Tn / 128, 1, Bn * Hn), 256, SMEM_G(64)>>>(
            S, Vt, nullptr, O, Tn, Tn, Tn, En,
            Hn, (long long)Hn * TnTn, TnTn,
            (long long)Hn * Dh * Tn, (long long)Dh * Tn,
            TnE, (long long)Dh, 1.0f, 0);

        // attn proj
        mma_nt<128, 0><<<dim3(ROWS / 128, En / 128, 1), 256, SMEM_G(128)>>>(
            O, wo, bo + (size_t)l * En, Q, En, En, En, En,
            1, 0, 0, 0, 0, 0, 0, 1.0f, 0);
        add_layernorm<<<ROWS, 256>>>(Q, X, ln1_g + (size_t)l * En, ln1_b + (size_t)l * En, X);

        // FFN
        mma_nt<128, 0><<<dim3(ROWS / 128, FFn / 128, 1), 256, SMEM_G(128)>>>(
            X, w1, b1 + (size_t)l * FFn, FF, En, En, En, FFn,
            1, 0, 0, 0, 0, 0, 0, 1.0f, 1);   // fused exact GELU
        mma_nt<128, 0><<<dim3(ROWS / 128, En / 128, 1), 256, SMEM_G(128)>>>(
            FF, w2, b2 + (size_t)l * En, Q, FFn, FFn, FFn, En,
            1, 0, 0, 0, 0, 0, 0, 1.0f, 0);
        add_layernorm<<<ROWS, 256>>>(Q, X, ln2_g + (size_t)l * En, ln2_b + (size_t)l * En, X);
    }

    add_layernorm<<<ROWS, 256>>>(X, nullptr, lnf_g, lnf_b, X);

    // LM head
    mma_nt<128, 0><<<dim3(ROWS / 128, Vn / 128, 1), 256, SMEM_G(128)>>>(
        X, lm_w, lm_b, logits, En, En, En, Vn,
        1, 0, 0, 0, 0, 0, 0, 1.0f, 0);

    loss_rows<<<ROWS, 256>>>(logits, tgt, RL);
    if (loss_idx >= 0)
        loss_reduce<<<1, 256>>>(RL, ((float*)d_out) + loss_idx);
}

// round 12
// speedup vs baseline: 1.8395x; 1.1224x over previous
#include <cuda_runtime.h>
#include <cuda_bf16.h>
#include <math.h>
#include <cstdint>

// ---------------- problem constants ----------------
#define Vn 32000
#define En 1024
#define Tn 2048
#define Hn 16
#define Dh 64
#define Ln 4
#define FFn 4096
#define Bn 4
#define ROWS (Bn * Tn)          // 8192
#define NHEADTOK (ROWS * Hn)    // 131072

// ---------------- scratch (static device memory) -------------------------
#define SZ_X   ((size_t)ROWS * En)
#define OFF_X  ((size_t)0)
#define OFF_Q  (OFF_X + SZ_X)
#define OFF_K  (OFF_Q + SZ_X)
#define OFF_V  (OFF_K + SZ_X)
#define OFF_O  (OFF_V + SZ_X)
#define OFF_FF (OFF_O + SZ_X)                    // ROWS*FFn floats; reused as Vt during attention
#define OFF_S  (OFF_FF + (size_t)ROWS * FFn)
#define OFF_RL (OFF_S + (size_t)Bn * Hn * Tn * Tn)
// rounded-weight copies (tf32 grid), filled by round_copy each launch
#define SZ_QKVW ((size_t)Ln * Dh * Dh)
#define OFF_WQR (OFF_RL + ROWS + 64)
#define OFF_WKR (OFF_WQR + SZ_QKVW)
#define OFF_WVR (OFF_WKR + SZ_QKVW)
#define OFF_WOR (OFF_WVR + SZ_QKVW)
#define OFF_W1R (OFF_WOR + (size_t)Ln * En * En)
#define OFF_W2R (OFF_W1R + (size_t)Ln * FFn * En)
#define OFF_LMR (OFF_W2R + (size_t)Ln * En * FFn)
#define TOTALF  (OFF_LMR + (size_t)Vn * En + 64)

__device__ float g_buf[TOTALF];
__device__ int   g_flags[2];

// =================== helpers (all baseline PTX, proven in R7/R8/R11) ======
__device__ __forceinline__ uint32_t smem_u32(const void* p) {
    uint32_t a;
    asm("{ .reg .u64 t; cvta.to.shared.u64 t, %1; cvt.u32.u64 %0, t; }" : "=r"(a) : "l"(p));
    return a;
}
__device__ __forceinline__ uint32_t cvt1(float f) {
    uint32_t u;
    asm("cvt.rna.tf32.f32 %0, %1;" : "=r"(u) : "f"(f));
    return u;
}
__device__ __forceinline__ uint4 tf32x4(float4 v) {
    uint4 w;
    w.x = cvt1(v.x); w.y = cvt1(v.y); w.z = cvt1(v.z); w.w = cvt1(v.w);
    return w;
}
__device__ __forceinline__ void cp16(uint32_t dst, const float* src) {
    asm volatile("cp.async.ca.shared.global [%0], [%1], 16;" :: "r"(dst), "l"(src));
}
#define CP_COMMIT() asm volatile("cp.async.commit_group;" ::: "memory")
#define CP_WAIT0()  asm volatile("cp.async.wait_group 0;" ::: "memory")

__device__ __forceinline__ void mma8(float c[4], const uint32_t a[4], const uint32_t b[2]) {
    asm volatile(
        "mma.sync.aligned.m16n8k8.row.col.f32.tf32.tf32.f32 "
        "{%0,%1,%2,%3}, {%4,%5,%6,%7}, {%8,%9}, {%0,%1,%2,%3};"
        : "+f"(c[0]), "+f"(c[1]), "+f"(c[2]), "+f"(c[3])
        : "r"(a[0]), "r"(a[1]), "r"(a[2]), "r"(a[3]), "r"(b[0]), "r"(b[1]));
}

// =================== warp-mma tf32 NT GEMM ================================
// C[M,N] = alpha*(A[M,K] @ B[N,K]^T) + bias, optional exact GELU.
// BM=128, BN in {64,128}, BK=32, 8 warps (4x2). Batched over z=z1*z2dim+z2.
// CAUSAL: 0 none, 1 skip tiles n0>m0 (scores), 2 cap K at m0+128 (A*V).
// APURE: A already tf32-rounded in gmem -> cp.async A (no staging/cvt).
// B is ALWAYS tf32-rounded in gmem -> cp.async B.
// ROUNDC: round epilogue output to tf32 grid (for pure downstream consumers).
template<int BN, int CAUSAL, int APURE, int ROUNDC>
__global__ void __launch_bounds__(256)
mma_nt(const float* __restrict__ A, const float* __restrict__ B,
       const float* __restrict__ bias, float* __restrict__ C,
       int K, int lda, int ldb, int ldc,
       int z2dim,
       long long sA1, long long sA2, long long sB1, long long sB2,
       long long sC1, long long sC2,
       float alpha, int fuse_gelu)
{
    constexpr int BM = 128, BK = 32, SP = BK + 4;   // padded stride (floats)
    constexpr int WN = BN / 2;                      // warp n-extent (4x2 warps)
    constexpr int NT = WN / 8;                      // n8 tiles per warp
    constexpr int NB = BN / 32;                     // B 16B chunks per thread

    const int m0 = blockIdx.x * BM;
    const int n0 = blockIdx.y * BN;
    if (CAUSAL == 1 && n0 > m0) return;

    {
        int bz = blockIdx.z;
        int z1 = bz / z2dim, z2 = bz - z1 * z2dim;
        A += z1 * sA1 + z2 * sA2;
        B += z1 * sB1 + z2 * sB2;
        C += z1 * sC1 + z2 * sC2;
    }
    const int Keff = (CAUSAL == 2) ? min(K, m0 + BM) : K;

    extern __shared__ float sm[];
    const uint32_t sbase = smem_u32(sm);
    float* As0 = sm;                               // [2][BM*SP]
    float* Bs0 = sm + 2 * BM * SP;                 // [2][BN*SP]

    const int tid = threadIdx.x;
    const int wid = tid >> 5, lane = tid & 31;
    const int wm = wid & 3, wn = wid >> 2;
    const int grp = lane >> 2, tig = lane & 3;

    float acc[2][NT][4];
#pragma unroll
    for (int mt = 0; mt < 2; mt++)
#pragma unroll
        for (int nt = 0; nt < NT; nt++)
#pragma unroll
            for (int j = 0; j < 4; j++) acc[mt][nt][j] = 0.f;

    float4 aR[4];

    // ---- A via LDG registers (mixed path) ----
    auto loadA = [&](int kt) {
        const int k0 = kt * BK;
#pragma unroll
        for (int i = 0; i < 4; i++) {              // 128 rows x 8 chunks
            int f = tid + i * 256;
            int r = f >> 3, c4 = (f & 7) * 4;
            aR[i] = *(const float4*)(A + (long long)(m0 + r) * lda + k0 + c4);
        }
    };
    auto storeA = [&](int s) {
        float* As = As0 + s * BM * SP;
#pragma unroll
        for (int i = 0; i < 4; i++) {
            int f = tid + i * 256;
            int r = f >> 3, c4 = (f & 7) * 4;
            *(uint4*)&As[r * SP + c4] = tf32x4(aR[i]);
        }
    };
    // ---- A via cp.async (pure path) ----
    auto cpA = [&](int kt, int s) {
        const int k0 = kt * BK;
        const uint32_t abase = sbase + (uint32_t)(s * BM * SP) * 4;
#pragma unroll
        for (int i = 0; i < 4; i++) {
            int f = tid + i * 256;
            int r = f >> 3, c4 = (f & 7) * 4;
            cp16(abase + (uint32_t)(r * SP + c4) * 4,
                 A + (long long)(m0 + r) * lda + k0 + c4);
        }
    };
    // ---- B via cp.async (always) ----
    auto cpB = [&](int kt, int s) {
        const int k0 = kt * BK;
        const uint32_t bbase = sbase + (uint32_t)((2 * BM + s * BN) * SP) * 4;
#pragma unroll
        for (int i = 0; i < NB; i++) {
            int f = tid + i * 256;
            int r = f >> 3, c4 = (f & 7) * 4;
            cp16(bbase + (uint32_t)(r * SP + c4) * 4,
                 B + (long long)(n0 + r) * ldb + k0 + c4);
        }
    };
    auto compute = [&](int s) {
        const uint32_t* Au = (const uint32_t*)(As0 + s * BM * SP);
        const uint32_t* Bu = (const uint32_t*)(Bs0 + s * BN * SP);
#pragma unroll
        for (int ks = 0; ks < 4; ks++) {
            const int kb = ks * 8;
            uint32_t af[2][4];
#pragma unroll
            for (int mt = 0; mt < 2; mt++) {
                int row = wm * 32 + mt * 16;
                af[mt][0] = Au[(row + grp) * SP + kb + tig];
                af[mt][1] = Au[(row + grp + 8) * SP + kb + tig];
                af[mt][2] = Au[(row + grp) * SP + kb + tig + 4];
                af[mt][3] = Au[(row + grp + 8) * SP + kb + tig + 4];
            }
            uint32_t bf[NT][2];
#pragma unroll
            for (int nt = 0; nt < NT; nt++) {
                int col = wn * WN + nt * 8 + grp;
                bf[nt][0] = Bu[col * SP + kb + tig];
                bf[nt][1] = Bu[col * SP + kb + tig + 4];
            }
#pragma unroll
            for (int mt = 0; mt < 2; mt++)
#pragma unroll
                for (int nt = 0; nt < NT; nt++)
                    mma8(acc[mt][nt], af[mt], bf[nt]);
        }
    };

    const int nkt = Keff / BK;
    // prologue
    if (APURE) cpA(0, 0); else loadA(0);
    cpB(0, 0);
    CP_COMMIT();
    if (!APURE) storeA(0);
    CP_WAIT0();
    __syncthreads();

    for (int kt = 0; kt < nkt; kt++) {
        const int s = kt & 1;
        if (kt + 1 < nkt) {
            if (APURE) cpA(kt + 1, s ^ 1); else loadA(kt + 1);
            cpB(kt + 1, s ^ 1);
            CP_COMMIT();
        }
        compute(s);
        if (kt + 1 < nkt) {
            if (!APURE) storeA(s ^ 1);
            CP_WAIT0();
            __syncthreads();
        }
    }

    // ---- epilogue ----
#pragma unroll
    for (int mt = 0; mt < 2; mt++) {
#pragma unroll
        for (int nt = 0; nt < NT; nt++) {
            const int col = n0 + wn * WN + nt * 8 + tig * 2;
            float b0 = bias ? bias[col] : 0.f;
            float b1 = bias ? bias[col + 1] : 0.f;
#pragma unroll
            for (int h = 0; h < 2; h++) {
                const long long row = m0 + wm * 32 + mt * 16 + grp + h * 8;
                float v0 = acc[mt][nt][h * 2 + 0] * alpha + b0;
                float v1 = acc[mt][nt][h * 2 + 1] * alpha + b1;
                if (fuse_gelu) {
                    v0 = 0.5f * v0 * (1.0f + erff(v0 * 0.70710678118654752f));
                    v1 = 0.5f * v1 * (1.0f + erff(v1 * 0.70710678118654752f));
                }
                if (ROUNDC) {
                    v0 = __uint_as_float(cvt1(v0));
                    v1 = __uint_as_float(cvt1(v1));
                }
                *(float2*)(C + row * ldc + col) = make_float2(v0, v1);
            }
        }
    }
}

#define SMEM_G(BN) (2 * (128 + (BN)) * 36 * 4)

// =================== small kernels ========================================
__global__ void round_copy(const float* __restrict__ s, float* __restrict__ d,
                           long long n) {
    for (long long i = blockIdx.x * (long long)blockDim.x + threadIdx.x;
         i < n; i += (long long)gridDim.x * blockDim.x)
        d[i] = __uint_as_float(cvt1(s[i]));
}

__global__ void detect_kernel(const void* idxp) {
    __shared__ int bad;
    if (threadIdx.x == 0) bad = 0;
    __syncthreads();
    const long long* p = (const long long*)idxp;
    for (int i = threadIdx.x; i < ROWS / 2; i += blockDim.x) {
        long long v = p[i];
        if (v < 0 || v >= Vn) bad = 1;
    }
    __syncthreads();
    if (threadIdx.x == 0) g_flags[0] = bad ? 0 : 1;
}

__device__ __forceinline__ long long read_token(const void* p, int i) {
    if (g_flags[0]) return ((const long long*)p)[i];
    return (long long)((const int*)p)[i];
}

__global__ void embed_kernel(const void* idxp, const float* __restrict__ tok,
                             const float* __restrict__ pos, float* __restrict__ x) {
    int row = blockIdx.x;
    int t = row % Tn;
    long long token = read_token(idxp, row);
    const float* te = tok + (size_t)token * En;
    const float* pe = pos + (size_t)t * En;
    float* xo = x + (size_t)row * En;
#pragma unroll
    for (int i = 0; i < En / 256; i++) {
        int c = threadIdx.x + i * 256;
        xo[c] = te[c] + pe[c];
    }
}

// V [B,T,H,Dh] -> Vt [B,H,Dh,T] (values already tf32-rounded by qkv epilogue)
__global__ void transpose_v(const float* __restrict__ V, float* __restrict__ Vt) {
    __shared__ float tile[32][33];
    int bh = blockIdx.z;
    int b = bh / Hn, h = bh - b * Hn;
    int t0 = blockIdx.x * 32, d0 = blockIdx.y * 32;
    int tx = threadIdx.x, ty0 = threadIdx.y;
#pragma unroll
    for (int i = 0; i < 4; i++) {
        int ty = ty0 + i * 8;
        tile[ty][tx] = V[((size_t)(b * Tn + t0 + ty) * Hn + h) * Dh + d0 + tx];
    }
    __syncthreads();
#pragma unroll
    for (int i = 0; i < 4; i++) {
        int ty = ty0 + i * 8;
        Vt[((size_t)(b * Hn + h) * Dh + d0 + ty) * Tn + t0 + tx] = tile[tx][ty];
    }
}

// causal softmax; stores tf32-rounded probs (AV GEMM consumes them raw)
__global__ void softmax_causal(float* __restrict__ S) {
    long long row = blockIdx.x;
    int i = (int)(row % Tn);
    float* p = S + row * (long long)Tn;
    int n = i + 1;
    int jend = (i & ~127) + 128;         // A*V never reads past this row-tile's K cap
    int tid = threadIdx.x;
    __shared__ float red[256];

    float mx = -1e30f;
    for (int j = tid; j < n; j += 256) mx = fmaxf(mx, p[j]);
    red[tid] = mx; __syncthreads();
    for (int s = 128; s > 0; s >>= 1) { if (tid < s) red[tid] = fmaxf(red[tid], red[tid + s]); __syncthreads(); }
    mx = red[0]; __syncthreads();

    float sum = 0.f;
    for (int j = tid; j < n; j += 256) sum += expf(p[j] - mx);
    red[tid] = sum; __syncthreads();
    for (int s = 128; s > 0; s >>= 1) { if (tid < s) red[tid] += red[tid + s]; __syncthreads(); }
    float inv = 1.0f / red[0];

    for (int j = tid; j < n; j += 256) p[j] = __uint_as_float(cvt1(expf(p[j] - mx) * inv));
    for (int j = n + tid; j < jend; j += 256) p[j] = 0.f;
}

__global__ void add_layernorm(const float* __restrict__ a, const float* __restrict__ res,
                              const float* __restrict__ g, const float* __restrict__ b,
                              float* __restrict__ out)
{
    int row = blockIdx.x;
    const float* pa = a + (size_t)row * En;
    const float* pr = res ? res + (size_t)row * En : nullptr;
    float* po = out + (size_t)row * En;
    int tid = threadIdx.x;
    __shared__ float red[256];
    float v[En / 256];

    float s = 0.f;
#pragma unroll
    for (int i = 0; i < En / 256; i++) {
        int c = tid + i * 256;
        float x = pa[c] + (pr ? pr[c] : 0.f);
        v[i] = x; s += x;
    }
    red[tid] = s; __syncthreads();
    for (int st = 128; st > 0; st >>= 1) { if (tid < st) red[tid] += red[tid + st]; __syncthreads(); }
    float mean = red[0] * (1.0f / En); __syncthreads();

    float s2 = 0.f;
#pragma unroll
    for (int i = 0; i < En / 256; i++) { float d = v[i] - mean; s2 += d * d; }
    red[tid] = s2; __syncthreads();
    for (int st = 128; st > 0; st >>= 1) { if (tid < st) red[tid] += red[tid + st]; __syncthreads(); }
    float inv = rsqrtf(red[0] * (1.0f / En) + 1e-5f);

#pragma unroll
    for (int i = 0; i < En / 256; i++) {
        int c = tid + i * 256;
        po[c] = (v[i] - mean) * inv * g[c] + b[c];
    }
}

// single-pass online logsumexp loss per row
__global__ void loss_rows(const float* __restrict__ logits, const void* tgt,
                          float* __restrict__ rowloss)
{
    int r = blockIdx.x;
    const float* p = logits + (size_t)r * Vn;
    int tid = threadIdx.x;
    __shared__ float rm[256], rs[256];

    float m = -1e30f, s = 0.f;
    for (int j = tid; j < Vn; j += 256) {
        float x = p[j];
        if (x > m) { s = s * expf(m - x) + 1.f; m = x; }
        else s += expf(x - m);
    }
    rm[tid] = m; rs[tid] = s; __syncthreads();
    for (int st = 128; st > 0; st >>= 1) {
        if (tid < st) {
            float m2 = rm[tid + st], s2 = rs[tid + st];
            float M = fmaxf(rm[tid], m2);
            rs[tid] = rs[tid] * expf(rm[tid] - M) + s2 * expf(m2 - M);
            rm[tid] = M;
        }
        __syncthreads();
    }
    if (tid == 0) {
        long long t = read_token(tgt, r);
        rowloss[r] = logf(rs[0]) + rm[0] - p[t];
    }
}

__global__ void loss_reduce(const float* __restrict__ rowloss, float* __restrict__ out) {
    __shared__ float red[256];
    int tid = threadIdx.x;
    float s = 0.f;
    for (int i = tid; i < ROWS; i += 256) s += rowloss[i];
    red[tid] = s; __syncthreads();
    for (int st = 128; st > 0; st >>= 1) { if (tid < st) red[tid] += red[tid + st]; __syncthreads(); }
    if (tid == 0) out[0] = red[0] * (1.0f / ROWS);
}

// =================== host orchestration ===================================
extern "C" void kernel_launch(void* const* d_in, const int* in_sizes, int n_in,
                              void* d_out, int out_size)
{
    const void*  idx     = d_in[0];
    const void*  tgt     = d_in[1];
    const float* tok_emb = (const float*)d_in[2];
    const float* pos_emb = (const float*)d_in[3];
    const float* Wq      = (const float*)d_in[4];
    const float* Wk      = (const float*)d_in[5];
    const float* Wv      = (const float*)d_in[6];
    const float* Wo      = (const float*)d_in[7];
    const float* bo      = (const float*)d_in[8];
    const float* ln1_g   = (const float*)d_in[9];
    const float* ln1_b   = (const float*)d_in[10];
    const float* W1      = (const float*)d_in[11];
    const float* b1      = (const float*)d_in[12];
    const float* W2      = (const float*)d_in[13];
    const float* b2      = (const float*)d_in[14];
    const float* ln2_g   = (const float*)d_in[15];
    const float* ln2_b   = (const float*)d_in[16];
    const float* lnf_g   = (const float*)d_in[17];
    const float* lnf_b   = (const float*)d_in[18];
    const float* lm_w    = (const float*)d_in[19];
    const float* lm_b    = (const float*)d_in[20];

    cudaFuncSetAttribute(mma_nt<64, 0, 0, 1>,  cudaFuncAttributeMaxDynamicSharedMemorySize, SMEM_G(64));
    cudaFuncSetAttribute(mma_nt<128, 1, 1, 0>, cudaFuncAttributeMaxDynamicSharedMemorySize, SMEM_G(128));
    cudaFuncSetAttribute(mma_nt<64, 2, 1, 1>,  cudaFuncAttributeMaxDynamicSharedMemorySize, SMEM_G(64));
    cudaFuncSetAttribute(mma_nt<128, 0, 1, 0>, cudaFuncAttributeMaxDynamicSharedMemorySize, SMEM_G(128));
    cudaFuncSetAttribute(mma_nt<128, 0, 0, 1>, cudaFuncAttributeMaxDynamicSharedMemorySize, SMEM_G(128));
    cudaFuncSetAttribute(mma_nt<128, 0, 0, 0>, cudaFuncAttributeMaxDynamicSharedMemorySize, SMEM_G(128));

    float* buf = nullptr;
    cudaGetSymbolAddress((void**)&buf, g_buf);
    float* X  = buf + OFF_X;
    float* Q  = buf + OFF_Q;
    float* Kb = buf + OFF_K;
    float* Vb = buf + OFF_V;
    float* O  = buf + OFF_O;
    float* FF = buf + OFF_FF;     // also Vt scratch during attention
    float* Vt = FF;
    float* S  = buf + OFF_S;
    float* RL = buf + OFF_RL;
    float* WQR = buf + OFF_WQR;
    float* WKR = buf + OFF_WKR;
    float* WVR = buf + OFF_WVR;
    float* WOR = buf + OFF_WOR;
    float* W1R = buf + OFF_W1R;
    float* W2R = buf + OFF_W2R;
    float* LMR = buf + OFF_LMR;

    const size_t NLOG = (size_t)ROWS * Vn;
    float* logits;
    long long loss_idx;
    if ((size_t)out_size >= NLOG + 1) { logits = (float*)d_out; loss_idx = (long long)NLOG; }
    else if ((size_t)out_size == NLOG) { logits = (float*)d_out; loss_idx = -1; }
    else { logits = S; loss_idx = 0; }

    detect_kernel<<<1, 256>>>(idx);
    embed_kernel<<<ROWS, 256>>>(idx, tok_emb, pos_emb, X);

    // pre-round all weights to the tf32 grid (makes consumer cvt a no-op)
    round_copy<<<64, 256>>>(Wq, WQR, (long long)SZ_QKVW);
    round_copy<<<64, 256>>>(Wk, WKR, (long long)SZ_QKVW);
    round_copy<<<64, 256>>>(Wv, WVR, (long long)SZ_QKVW);
    round_copy<<<512, 256>>>(Wo, WOR, (long long)Ln * En * En);
    round_copy<<<512, 256>>>(W1, W1R, (long long)Ln * FFn * En);
    round_copy<<<512, 256>>>(W2, W2R, (long long)Ln * En * FFn);
    round_copy<<<512, 256>>>(lm_w, LMR, (long long)Vn * En);

    const long long TnE  = (long long)Tn * En;
    const long long TnTn = (long long)Tn * Tn;

    for (int l = 0; l < Ln; l++) {
        const float* wq = WQR + (size_t)l * Dh * Dh;
        const float* wk = WKR + (size_t)l * Dh * Dh;
        const float* wv = WVR + (size_t)l * Dh * Dh;
        const float* wo = WOR + (size_t)l * En * En;
        const float* w1 = W1R + (size_t)l * FFn * En;
        const float* w2 = W2R + (size_t)l * En * FFn;

        // q/k/v : mixed-A (X), rounded output (feeds pure GEMMs)
        dim3 gp(NHEADTOK / 128, 1, 1);
        mma_nt<64, 0, 0, 1><<<gp, 256, SMEM_G(64)>>>(X, wq, nullptr, Q,  Dh, Dh, Dh, Dh,
                                                     1, 0, 0, 0, 0, 0, 0, 1.0f, 0);
        mma_nt<64, 0, 0, 1><<<gp, 256, SMEM_G(64)>>>(X, wk, nullptr, Kb, Dh, Dh, Dh, Dh,
                                                     1, 0, 0, 0, 0, 0, 0, 1.0f, 0);
        mma_nt<64, 0, 0, 1><<<gp, 256, SMEM_G(64)>>>(X, wv, nullptr, Vb, Dh, Dh, Dh, Dh,
                                                     1, 0, 0, 0, 0, 0, 0, 1.0f, 0);
        transpose_v<<<dim3(Tn / 32, 2, Bn * Hn), dim3(32, 8)>>>(Vb, Vt);

        // scores = Q K^T / 8 : fully pure (Q,K rounded), raw fp32 out for softmax
        mma_nt<128, 1, 1, 0><<<dim3(Tn / 128, Tn / 128, Bn * Hn), 256, SMEM_G(128)>>>(
            Q, Kb, nullptr, S, Dh, En, En, Tn,
            Hn, TnE, (long long)Dh, TnE, (long long)Dh,
            (long long)Hn * TnTn, TnTn, 0.125f, 0);

        softmax_causal<<<Bn * Hn * Tn, 256>>>(S);

        // O = S @ Vt^T : fully pure (probs+V rounded), rounded out (feeds Wo)
        mma_nt<64, 2, 1, 1><<<dim3(Tn / 128, 1, Bn * Hn), 256, SMEM_G(64)>>>(
            S, Vt, nullptr, O, Tn, Tn, Tn, En,
            Hn, (long long)Hn * TnTn, TnTn,
            (long long)Hn * Dh * Tn, (long long)Dh * Tn,
            TnE, (long long)Dh, 1.0f, 0);

        // attn proj : pure (O rounded, wo rounded), raw out (feeds LN)
        mma_nt<128, 0, 1, 0><<<dim3(ROWS / 128, En / 128, 1), 256, SMEM_G(128)>>>(
            O, wo, bo + (size_t)l * En, Q, En, En, En, En,
            1, 0, 0, 0, 0, 0, 0, 1.0f, 0);
        add_layernorm<<<ROWS, 256>>>(Q, X, ln1_g + (size_t)l * En, ln1_b + (size_t)l * En, X);

        // FFN1 : mixed-A (X), fused GELU, rounded out (feeds pure FFN2)
        mma_nt<128, 0, 0, 1><<<dim3(ROWS / 128, FFn / 128, 1), 256, SMEM_G(128)>>>(
            X, w1, b1 + (size_t)l * FFn, FF, En, En, En, FFn,
            1, 0, 0, 0, 0, 0, 0, 1.0f, 1);
        // FFN2 : pure (FF rounded, w2 rounded), raw out (feeds LN)
        mma_nt<128, 0, 1, 0><<<dim3(ROWS / 128, En / 128, 1), 256, SMEM_G(128)>>>(
            FF, w2, b2 + (size_t)l * En, Q, FFn, FFn, FFn, En,
            1, 0, 0, 0, 0, 0, 0, 1.0f, 0);
        add_layernorm<<<ROWS, 256>>>(Q, X, ln2_g + (size_t)l * En, ln2_b + (size_t)l * En, X);
    }

    add_layernorm<<<ROWS, 256>>>(X, nullptr, lnf_g, lnf_b, X);

    // LM head : mixed-A (X), raw fp32 logits
    mma_nt<128, 0, 0, 0><<<dim3(ROWS / 128, Vn / 128, 1), 256, SMEM_G(128)>>>(
        X, LMR, lm_b, logits, En, En, En, Vn,
        1, 0, 0, 0, 0, 0, 0, 1.0f, 0);

    loss_rows<<<ROWS, 256>>>(logits, tgt, RL);
    if (loss_idx >= 0)
        loss_reduce<<<1, 256>>>(RL, ((float*)d_out) + loss_idx);
}

// round 13
// speedup vs baseline: 2.6866x; 1.4605x over previous
#include <cuda_runtime.h>
#include <cuda_fp16.h>
#include <math.h>
#include <cstdint>

// ---------------- problem constants ----------------
#define Vn 32000
#define En 1024
#define Tn 2048
#define Hn 16
#define Dh 64
#define Ln 4
#define FFn 4096
#define Bn 4
#define ROWS (Bn * Tn)          // 8192
#define NHEADTOK (ROWS * Hn)    // 131072

// ---------------- fp32 scratch -------------------------------------------
#define SZ_X   ((size_t)ROWS * En)
#define OFF_X  ((size_t)0)
#define OFF_QT (OFF_X + SZ_X)                       // fp32 GEMM outputs pre-LN
#define OFF_S  (OFF_QT + SZ_X)                      // raw attention scores
#define OFF_RL (OFF_S + (size_t)Bn * Hn * Tn * Tn)
#define TOTALF (OFF_RL + ROWS + 64)
__device__ float g_buf[TOTALF];

// ---------------- fp16 scratch -------------------------------------------
#define HSZ_QKV ((size_t)NHEADTOK * Dh)             // 8,388,608
#define HOFF_Q  ((size_t)0)
#define HOFF_K  (HOFF_Q + HSZ_QKV)
#define HOFF_V  (HOFF_K + HSZ_QKV)
#define HOFF_VT (HOFF_V + HSZ_QKV)
#define HOFF_O  (HOFF_VT + HSZ_QKV)
#define HOFF_FF (HOFF_O + HSZ_QKV)
#define HOFF_P  (HOFF_FF + (size_t)ROWS * FFn)      // softmax probs
#define HOFF_WQ (HOFF_P + (size_t)Bn * Hn * Tn * Tn)
#define HOFF_WK (HOFF_WQ + (size_t)Ln * Dh * Dh)
#define HOFF_WV (HOFF_WK + (size_t)Ln * Dh * Dh)
#define HOFF_WO (HOFF_WV + (size_t)Ln * Dh * Dh)
#define HOFF_W1 (HOFF_WO + (size_t)Ln * En * En)
#define HOFF_W2 (HOFF_W1 + (size_t)Ln * FFn * En)
#define HOFF_LM (HOFF_W2 + (size_t)Ln * En * FFn)
#define TOTALH  (HOFF_LM + (size_t)Vn * En + 64)
__device__ __half g_hbuf[TOTALH];

__device__ int g_flags[2];

// =================== helpers (baseline PTX) ===============================
__device__ __forceinline__ uint32_t smem_u32(const void* p) {
    uint32_t a;
    asm("{ .reg .u64 t; cvta.to.shared.u64 t, %1; cvt.u32.u64 %0, t; }" : "=r"(a) : "l"(p));
    return a;
}
__device__ __forceinline__ void cp16(uint32_t dst, const void* src) {
    asm volatile("cp.async.ca.shared.global [%0], [%1], 16;" :: "r"(dst), "l"(src));
}
#define CP_COMMIT() asm volatile("cp.async.commit_group;" ::: "memory")
#define CP_WAIT0()  asm volatile("cp.async.wait_group 0;" ::: "memory")

__device__ __forceinline__ void mma16(float c[4], const uint32_t a[4], const uint32_t b[2]) {
    asm volatile(
        "mma.sync.aligned.m16n8k16.row.col.f32.f16.f16.f32 "
        "{%0,%1,%2,%3}, {%4,%5,%6,%7}, {%8,%9}, {%0,%1,%2,%3};"
        : "+f"(c[0]), "+f"(c[1]), "+f"(c[2]), "+f"(c[3])
        : "r"(a[0]), "r"(a[1]), "r"(a[2]), "r"(a[3]), "r"(b[0]), "r"(b[1]));
}

// =================== warp-mma fp16 NT GEMM ================================
// C[M,N] = alpha*(A[M,K] @ B[N,K]^T) + bias, optional exact GELU.
// BM=128, BN in {64,128}, BK=32, 8 warps (4x2). Batched over z=z1*z2dim+z2.
// CAUSAL: 0 none, 1 skip tiles n0>m0 (scores), 2 cap K at m0+128 (A*V).
// APURE: A is fp16 in gmem -> cp.async. Else A fp32 -> reg-stage + cvt.
// B is ALWAYS fp16 in gmem -> cp.async.
// COUT: 1 = fp16 output, 0 = fp32 output.
template<int BN, int CAUSAL, int APURE, int COUT>
__global__ void __launch_bounds__(256)
mma_h(const void* __restrict__ Av, const __half* __restrict__ B,
      const float* __restrict__ bias, void* __restrict__ Cv,
      int K, int lda, int ldb, int ldc,
      int z2dim,
      long long sA1, long long sA2, long long sB1, long long sB2,
      long long sC1, long long sC2,
      float alpha, int fuse_gelu)
{
    constexpr int BM = 128, BK = 32, SPH = 40;      // padded stride (halves)
    constexpr int WN = BN / 2;                      // warp n-extent (4x2 warps)
    constexpr int NT = WN / 8;                      // n8 tiles per warp
    constexpr int NBC = BN / 64;                    // B 16B chunks per thread

    const int m0 = blockIdx.x * BM;
    const int n0 = blockIdx.y * BN;
    if (CAUSAL == 1 && n0 > m0) return;

    long long offA, offB, offC;
    {
        int bz = blockIdx.z;
        int z1 = bz / z2dim, z2 = bz - z1 * z2dim;
        offA = z1 * sA1 + z2 * sA2;
        offB = z1 * sB1 + z2 * sB2;
        offC = z1 * sC1 + z2 * sC2;
    }
    const __half* Ah = (const __half*)Av + (APURE ? offA : 0);
    const float*  Af = (const float*)Av + (APURE ? 0 : offA);
    B += offB;
    const int Keff = (CAUSAL == 2) ? min(K, m0 + BM) : K;

    extern __shared__ __half smh[];
    const uint32_t sbase = smem_u32(smh);
    __half* As0 = smh;                              // [2][BM*SPH]
    __half* Bs0 = smh + 2 * BM * SPH;               // [2][BN*SPH]

    const int tid = threadIdx.x;
    const int wid = tid >> 5, lane = tid & 31;
    const int wm = wid & 3, wn = wid >> 2;
    const int grp = lane >> 2, tig = lane & 3;

    float acc[2][NT][4];
#pragma unroll
    for (int mt = 0; mt < 2; mt++)
#pragma unroll
        for (int nt = 0; nt < NT; nt++)
#pragma unroll
            for (int j = 0; j < 4; j++) acc[mt][nt][j] = 0.f;

    float4 aR[4];

    // ---- A via LDG fp32 registers (mixed path) ----
    auto loadA = [&](int kt) {
        const int k0 = kt * BK;
#pragma unroll
        for (int i = 0; i < 4; i++) {               // 128 rows x 8 float4
            int f = tid + i * 256;
            int r = f >> 3, c4 = (f & 7) * 4;
            aR[i] = *(const float4*)(Af + (long long)(m0 + r) * lda + k0 + c4);
        }
    };
    auto storeA = [&](int s) {
        __half* As = As0 + s * BM * SPH;
#pragma unroll
        for (int i = 0; i < 4; i++) {
            int f = tid + i * 256;
            int r = f >> 3, c4 = (f & 7) * 4;
            __half2 h01 = __floats2half2_rn(aR[i].x, aR[i].y);
            __half2 h23 = __floats2half2_rn(aR[i].z, aR[i].w);
            uint2 u = make_uint2(*(uint32_t*)&h01, *(uint32_t*)&h23);
            *(uint2*)&As[r * SPH + c4] = u;
        }
    };
    // ---- A via cp.async fp16 (pure path) : 512 chunks of 16B ----
    auto cpA = [&](int kt, int s) {
        const int k0 = kt * BK;
        const uint32_t abase = sbase + (uint32_t)(s * BM * SPH) * 2;
#pragma unroll
        for (int i = 0; i < 2; i++) {
            int f = tid + i * 256;
            int r = f >> 2, c = f & 3;              // chunk c: 8 halves
            cp16(abase + (uint32_t)(r * SPH + c * 8) * 2,
                 Ah + (long long)(m0 + r) * lda + k0 + c * 8);
        }
    };
    // ---- B via cp.async fp16 (always) ----
    auto cpB = [&](int kt, int s) {
        const int k0 = kt * BK;
        const uint32_t bbase = sbase + (uint32_t)((2 * BM + s * BN) * SPH) * 2;
#pragma unroll
        for (int i = 0; i < NBC; i++) {
            int f = tid + i * 256;
            int r = f >> 2, c = f & 3;
            cp16(bbase + (uint32_t)(r * SPH + c * 8) * 2,
                 B + (long long)(n0 + r) * ldb + k0 + c * 8);
        }
    };
    auto compute = [&](int s) {
        const __half* As = As0 + s * BM * SPH;
        const __half* Bs = Bs0 + s * BN * SPH;
#pragma unroll
        for (int ks = 0; ks < 2; ks++) {            // two k16 steps per BK=32
            const int kb = ks * 16;
            uint32_t af[2][4];
#pragma unroll
            for (int mt = 0; mt < 2; mt++) {
                int row = wm * 32 + mt * 16;
                af[mt][0] = *(const uint32_t*)&As[(row + grp) * SPH + kb + 2 * tig];
                af[mt][1] = *(const uint32_t*)&As[(row + grp + 8) * SPH + kb + 2 * tig];
                af[mt][2] = *(const uint32_t*)&As[(row + grp) * SPH + kb + 2 * tig + 8];
                af[mt][3] = *(const uint32_t*)&As[(row + grp + 8) * SPH + kb + 2 * tig + 8];
            }
            uint32_t bf[NT][2];
#pragma unroll
            for (int nt = 0; nt < NT; nt++) {
                int col = wn * WN + nt * 8 + grp;
                bf[nt][0] = *(const uint32_t*)&Bs[col * SPH + kb + 2 * tig];
                bf[nt][1] = *(const uint32_t*)&Bs[col * SPH + kb + 2 * tig + 8];
            }
#pragma unroll
            for (int mt = 0; mt < 2; mt++)
#pragma unroll
                for (int nt = 0; nt < NT; nt++)
                    mma16(acc[mt][nt], af[mt], bf[nt]);
        }
    };

    const int nkt = Keff / BK;
    // prologue
    if (APURE) cpA(0, 0); else loadA(0);
    cpB(0, 0);
    CP_COMMIT();
    if (!APURE) storeA(0);
    CP_WAIT0();
    __syncthreads();

    for (int kt = 0; kt < nkt; kt++) {
        const int s = kt & 1;
        if (kt + 1 < nkt) {
            if (APURE) cpA(kt + 1, s ^ 1); else loadA(kt + 1);
            cpB(kt + 1, s ^ 1);
            CP_COMMIT();
        }
        compute(s);
        if (kt + 1 < nkt) {
            if (!APURE) storeA(s ^ 1);
            CP_WAIT0();
            __syncthreads();
        }
    }

    // ---- epilogue ----
#pragma unroll
    for (int mt = 0; mt < 2; mt++) {
#pragma unroll
        for (int nt = 0; nt < NT; nt++) {
            const int col = n0 + wn * WN + nt * 8 + tig * 2;
            float b0 = bias ? bias[col] : 0.f;
            float b1 = bias ? bias[col + 1] : 0.f;
#pragma unroll
            for (int h = 0; h < 2; h++) {
                const long long row = m0 + wm * 32 + mt * 16 + grp + h * 8;
                float v0 = acc[mt][nt][h * 2 + 0] * alpha + b0;
                float v1 = acc[mt][nt][h * 2 + 1] * alpha + b1;
                if (fuse_gelu) {
                    v0 = 0.5f * v0 * (1.0f + erff(v0 * 0.70710678118654752f));
                    v1 = 0.5f * v1 * (1.0f + erff(v1 * 0.70710678118654752f));
                }
                if (COUT) {
                    __half2 hv = __floats2half2_rn(v0, v1);
                    *(__half2*)((__half*)Cv + offC + row * ldc + col) = hv;
                } else {
                    *(float2*)((float*)Cv + offC + row * ldc + col) = make_float2(v0, v1);
                }
            }
        }
    }
}

#define SMEM_H(BN) (2 * (128 + (BN)) * 40 * 2)

// =================== small kernels ========================================
__global__ void h_copy(const float* __restrict__ s, __half* __restrict__ d,
                       long long n) {
    for (long long i = blockIdx.x * (long long)blockDim.x + threadIdx.x;
         i < n; i += (long long)gridDim.x * blockDim.x)
        d[i] = __float2half_rn(s[i]);
}

__global__ void detect_kernel(const void* idxp) {
    __shared__ int bad;
    if (threadIdx.x == 0) bad = 0;
    __syncthreads();
    const long long* p = (const long long*)idxp;
    for (int i = threadIdx.x; i < ROWS / 2; i += blockDim.x) {
        long long v = p[i];
        if (v < 0 || v >= Vn) bad = 1;
    }
    __syncthreads();
    if (threadIdx.x == 0) g_flags[0] = bad ? 0 : 1;
}

__device__ __forceinline__ long long read_token(const void* p, int i) {
    if (g_flags[0]) return ((const long long*)p)[i];
    return (long long)((const int*)p)[i];
}

__global__ void embed_kernel(const void* idxp, const float* __restrict__ tok,
                             const float* __restrict__ pos, float* __restrict__ x) {
    int row = blockIdx.x;
    int t = row % Tn;
    long long token = read_token(idxp, row);
    const float* te = tok + (size_t)token * En;
    const float* pe = pos + (size_t)t * En;
    float* xo = x + (size_t)row * En;
#pragma unroll
    for (int i = 0; i < En / 256; i++) {
        int c = threadIdx.x + i * 256;
        xo[c] = te[c] + pe[c];
    }
}

// V [B,T,H,Dh] fp16 -> Vt [B,H,Dh,T] fp16
__global__ void transpose_v(const __half* __restrict__ V, __half* __restrict__ Vt) {
    __shared__ __half tile[32][33];
    int bh = blockIdx.z;
    int b = bh / Hn, h = bh - b * Hn;
    int t0 = blockIdx.x * 32, d0 = blockIdx.y * 32;
    int tx = threadIdx.x, ty0 = threadIdx.y;
#pragma unroll
    for (int i = 0; i < 4; i++) {
        int ty = ty0 + i * 8;
        tile[ty][tx] = V[((size_t)(b * Tn + t0 + ty) * Hn + h) * Dh + d0 + tx];
    }
    __syncthreads();
#pragma unroll
    for (int i = 0; i < 4; i++) {
        int ty = ty0 + i * 8;
        Vt[((size_t)(b * Hn + h) * Dh + d0 + ty) * Tn + t0 + tx] = tile[tx][ty];
    }
}

// causal softmax: read fp32 raw scores, write fp16 probs
__global__ void softmax_causal(const float* __restrict__ S, __half* __restrict__ P) {
    long long row = blockIdx.x;
    int i = (int)(row % Tn);
    const float* p = S + row * (long long)Tn;
    __half* q = P + row * (long long)Tn;
    int n = i + 1;
    int jend = (i & ~127) + 128;         // A*V never reads past this row-tile's K cap
    int tid = threadIdx.x;
    __shared__ float red[256];

    float mx = -1e30f;
    for (int j = tid; j < n; j += 256) mx = fmaxf(mx, p[j]);
    red[tid] = mx; __syncthreads();
    for (int s = 128; s > 0; s >>= 1) { if (tid < s) red[tid] = fmaxf(red[tid], red[tid + s]); __syncthreads(); }
    mx = red[0]; __syncthreads();

    float sum = 0.f;
    for (int j = tid; j < n; j += 256) sum += expf(p[j] - mx);
    red[tid] = sum; __syncthreads();
    for (int s = 128; s > 0; s >>= 1) { if (tid < s) red[tid] += red[tid + s]; __syncthreads(); }
    float inv = 1.0f / red[0];

    for (int j = tid; j < n; j += 256) q[j] = __float2half_rn(expf(p[j] - mx) * inv);
    for (int j = n + tid; j < jend; j += 256) q[j] = __float2half_rn(0.f);
}

__global__ void add_layernorm(const float* __restrict__ a, const float* __restrict__ res,
                              const float* __restrict__ g, const float* __restrict__ b,
                              float* __restrict__ out)
{
    int row = blockIdx.x;
    const float* pa = a + (size_t)row * En;
    const float* pr = res ? res + (size_t)row * En : nullptr;
    float* po = out + (size_t)row * En;
    int tid = threadIdx.x;
    __shared__ float red[256];
    float v[En / 256];

    float s = 0.f;
#pragma unroll
    for (int i = 0; i < En / 256; i++) {
        int c = tid + i * 256;
        float x = pa[c] + (pr ? pr[c] : 0.f);
        v[i] = x; s += x;
    }
    red[tid] = s; __syncthreads();
    for (int st = 128; st > 0; st >>= 1) { if (tid < st) red[tid] += red[tid + st]; __syncthreads(); }
    float mean = red[0] * (1.0f / En); __syncthreads();

    float s2 = 0.f;
#pragma unroll
    for (int i = 0; i < En / 256; i++) { float d = v[i] - mean; s2 += d * d; }
    red[tid] = s2; __syncthreads();
    for (int st = 128; st > 0; st >>= 1) { if (tid < st) red[tid] += red[tid + st]; __syncthreads(); }
    float inv = rsqrtf(red[0] * (1.0f / En) + 1e-5f);

#pragma unroll
    for (int i = 0; i < En / 256; i++) {
        int c = tid + i * 256;
        po[c] = (v[i] - mean) * inv * g[c] + b[c];
    }
}

// single-pass online logsumexp loss per row
__global__ void loss_rows(const float* __restrict__ logits, const void* tgt,
                          float* __restrict__ rowloss)
{
    int r = blockIdx.x;
    const float* p = logits + (size_t)r * Vn;
    int tid = threadIdx.x;
    __shared__ float rm[256], rs[256];

    float m = -1e30f, s = 0.f;
    for (int j = tid; j < Vn; j += 256) {
        float x = p[j];
        if (x > m) { s = s * expf(m - x) + 1.f; m = x; }
        else s += expf(x - m);
    }
    rm[tid] = m; rs[tid] = s; __syncthreads();
    for (int st = 128; st > 0; st >>= 1) {
        if (tid < st) {
            float m2 = rm[tid + st], s2 = rs[tid + st];
            float M = fmaxf(rm[tid], m2);
            rs[tid] = rs[tid] * expf(rm[tid] - M) + s2 * expf(m2 - M);
            rm[tid] = M;
        }
        __syncthreads();
    }
    if (tid == 0) {
        long long t = read_token(tgt, r);
        rowloss[r] = logf(rs[0]) + rm[0] - p[t];
    }
}

__global__ void loss_reduce(const float* __restrict__ rowloss, float* __restrict__ out) {
    __shared__ float red[256];
    int tid = threadIdx.x;
    float s = 0.f;
    for (int i = tid; i < ROWS; i += 256) s += rowloss[i];
    red[tid] = s; __syncthreads();
    for (int st = 128; st > 0; st >>= 1) { if (tid < st) red[tid] += red[tid + st]; __syncthreads(); }
    if (tid == 0) out[0] = red[0] * (1.0f / ROWS);
}

// =================== host orchestration ===================================
extern "C" void kernel_launch(void* const* d_in, const int* in_sizes, int n_in,
                              void* d_out, int out_size)
{
    const void*  idx     = d_in[0];
    const void*  tgt     = d_in[1];
    const float* tok_emb = (const float*)d_in[2];
    const float* pos_emb = (const float*)d_in[3];
    const float* Wq      = (const float*)d_in[4];
    const float* Wk      = (const float*)d_in[5];
    const float* Wv      = (const float*)d_in[6];
    const float* Wo      = (const float*)d_in[7];
    const float* bo      = (const float*)d_in[8];
    const float* ln1_g   = (const float*)d_in[9];
    const float* ln1_b   = (const float*)d_in[10];
    const float* W1      = (const float*)d_in[11];
    const float* b1      = (const float*)d_in[12];
    const float* W2      = (const float*)d_in[13];
    const float* b2      = (const float*)d_in[14];
    const float* ln2_g   = (const float*)d_in[15];
    const float* ln2_b   = (const float*)d_in[16];
    const float* lnf_g   = (const float*)d_in[17];
    const float* lnf_b   = (const float*)d_in[18];
    const float* lm_w    = (const float*)d_in[19];
    const float* lm_b    = (const float*)d_in[20];

    cudaFuncSetAttribute(mma_h<64, 0, 0, 1>,  cudaFuncAttributeMaxDynamicSharedMemorySize, SMEM_H(64));
    cudaFuncSetAttribute(mma_h<128, 1, 1, 0>, cudaFuncAttributeMaxDynamicSharedMemorySize, SMEM_H(128));
    cudaFuncSetAttribute(mma_h<64, 2, 1, 1>,  cudaFuncAttributeMaxDynamicSharedMemorySize, SMEM_H(64));
    cudaFuncSetAttribute(mma_h<128, 0, 1, 0>, cudaFuncAttributeMaxDynamicSharedMemorySize, SMEM_H(128));
    cudaFuncSetAttribute(mma_h<128, 0, 0, 1>, cudaFuncAttributeMaxDynamicSharedMemorySize, SMEM_H(128));
    cudaFuncSetAttribute(mma_h<128, 0, 0, 0>, cudaFuncAttributeMaxDynamicSharedMemorySize, SMEM_H(128));

    float* buf = nullptr;
    cudaGetSymbolAddress((void**)&buf, g_buf);
    __half* hb = nullptr;
    cudaGetSymbolAddress((void**)&hb, g_hbuf);

    float* X  = buf + OFF_X;
    float* QT = buf + OFF_QT;
    float* S  = buf + OFF_S;
    float* RL = buf + OFF_RL;

    __half* Qh  = hb + HOFF_Q;
    __half* Kh  = hb + HOFF_K;
    __half* Vh  = hb + HOFF_V;
    __half* Vth = hb + HOFF_VT;
    __half* Oh  = hb + HOFF_O;
    __half* FFh = hb + HOFF_FF;
    __half* Ph  = hb + HOFF_P;
    __half* WQh = hb + HOFF_WQ;
    __half* WKh = hb + HOFF_WK;
    __half* WVh = hb + HOFF_WV;
    __half* WOh = hb + HOFF_WO;
    __half* W1h = hb + HOFF_W1;
    __half* W2h = hb + HOFF_W2;
    __half* LMh = hb + HOFF_LM;

    const size_t NLOG = (size_t)ROWS * Vn;
    float* logits;
    long long loss_idx;
    if ((size_t)out_size >= NLOG + 1) { logits = (float*)d_out; loss_idx = (long long)NLOG; }
    else if ((size_t)out_size == NLOG) { logits = (float*)d_out; loss_idx = -1; }
    else { logits = S; loss_idx = 0; }

    detect_kernel<<<1, 256>>>(idx);
    embed_kernel<<<ROWS, 256>>>(idx, tok_emb, pos_emb, X);

    // pre-convert all weights to fp16
    h_copy<<<64, 256>>>(Wq, WQh, (long long)Ln * Dh * Dh);
    h_copy<<<64, 256>>>(Wk, WKh, (long long)Ln * Dh * Dh);
    h_copy<<<64, 256>>>(Wv, WVh, (long long)Ln * Dh * Dh);
    h_copy<<<512, 256>>>(Wo, WOh, (long long)Ln * En * En);
    h_copy<<<512, 256>>>(W1, W1h, (long long)Ln * FFn * En);
    h_copy<<<512, 256>>>(W2, W2h, (long long)Ln * En * FFn);
    h_copy<<<512, 256>>>(lm_w, LMh, (long long)Vn * En);

    const long long TnE  = (long long)Tn * En;
    const long long TnTn = (long long)Tn * Tn;

    for (int l = 0; l < Ln; l++) {
        const __half* wq = WQh + (size_t)l * Dh * Dh;
        const __half* wk = WKh + (size_t)l * Dh * Dh;
        const __half* wv = WVh + (size_t)l * Dh * Dh;
        const __half* wo = WOh + (size_t)l * En * En;
        const __half* w1 = W1h + (size_t)l * FFn * En;
        const __half* w2 = W2h + (size_t)l * En * FFn;

        // q/k/v : mixed-A (X fp32), fp16 output
        dim3 gp(NHEADTOK / 128, 1, 1);
        mma_h<64, 0, 0, 1><<<gp, 256, SMEM_H(64)>>>(X, wq, nullptr, Qh, Dh, Dh, Dh, Dh,
                                                    1, 0, 0, 0, 0, 0, 0, 1.0f, 0);
        mma_h<64, 0, 0, 1><<<gp, 256, SMEM_H(64)>>>(X, wk, nullptr, Kh, Dh, Dh, Dh, Dh,
                                                    1, 0, 0, 0, 0, 0, 0, 1.0f, 0);
        mma_h<64, 0, 0, 1><<<gp, 256, SMEM_H(64)>>>(X, wv, nullptr, Vh, Dh, Dh, Dh, Dh,
                                                    1, 0, 0, 0, 0, 0, 0, 1.0f, 0);
        transpose_v<<<dim3(Tn / 32, 2, Bn * Hn), dim3(32, 8)>>>(Vh, Vth);

        // scores = Q K^T / 8 : pure fp16 in, raw fp32 out for softmax
        mma_h<128, 1, 1, 0><<<dim3(Tn / 128, Tn / 128, Bn * Hn), 256, SMEM_H(128)>>>(
            Qh, Kh, nullptr, S, Dh, En, En, Tn,
            Hn, TnE, (long long)Dh, TnE, (long long)Dh,
            (long long)Hn * TnTn, TnTn, 0.125f, 0);

        softmax_causal<<<Bn * Hn * Tn, 256>>>(S, Ph);

        // O = P @ Vt^T : pure fp16 in, fp16 out, K capped causally
        mma_h<64, 2, 1, 1><<<dim3(Tn / 128, 1, Bn * Hn), 256, SMEM_H(64)>>>(
            Ph, Vth, nullptr, Oh, Tn, Tn, Tn, En,
            Hn, (long long)Hn * TnTn, TnTn,
            (long long)Hn * Dh * Tn, (long long)Dh * Tn,
            TnE, (long long)Dh, 1.0f, 0);

        // attn proj : pure fp16 in, fp32 out (feeds LN)
        mma_h<128, 0, 1, 0><<<dim3(ROWS / 128, En / 128, 1), 256, SMEM_H(128)>>>(
            Oh, wo, bo + (size_t)l * En, QT, En, En, En, En,
            1, 0, 0, 0, 0, 0, 0, 1.0f, 0);
        add_layernorm<<<ROWS, 256>>>(QT, X, ln1_g + (size_t)l * En, ln1_b + (size_t)l * En, X);

        // FFN1 : mixed-A (X fp32), GELU, fp16 out
        mma_h<128, 0, 0, 1><<<dim3(ROWS / 128, FFn / 128, 1), 256, SMEM_H(128)>>>(
            X, w1, b1 + (size_t)l * FFn, FFh, En, En, En, FFn,
            1, 0, 0, 0, 0, 0, 0, 1.0f, 1);
        // FFN2 : pure fp16 in, fp32 out
        mma_h<128, 0, 1, 0><<<dim3(ROWS / 128, En / 128, 1), 256, SMEM_H(128)>>>(
            FFh, w2, b2 + (size_t)l * En, QT, FFn, FFn, FFn, En,
            1, 0, 0, 0, 0, 0, 0, 1.0f, 0);
        add_layernorm<<<ROWS, 256>>>(QT, X, ln2_g + (size_t)l * En, ln2_b + (size_t)l * En, X);
    }

    add_layernorm<<<ROWS, 256>>>(X, nullptr, lnf_g, lnf_b, X);

    // LM head : mixed-A (X fp32), fp32 logits
    mma_h<128, 0, 0, 0><<<dim3(ROWS / 128, Vn / 128, 1), 256, SMEM_H(128)>>>(
        X, LMh, lm_b, logits, En, En, En, Vn,
        1, 0, 0, 0, 0, 0, 0, 1.0f, 0);

    loss_rows<<<ROWS, 256>>>(logits, tgt, RL);
    if (loss_idx >= 0)
        loss_reduce<<<1, 256>>>(RL, ((float*)d_out) + loss_idx);
}

// round 16
// speedup vs baseline: 2.7232x; 1.0136x over previous
#include <cuda_runtime.h>
#include <cuda_fp16.h>
#include <math.h>
#include <cstdint>

// ---------------- problem constants ----------------
#define Vn 32000
#define En 1024
#define Tn 2048
#define Hn 16
#define Dh 64
#define Ln 4
#define FFn 4096
#define Bn 4
#define ROWS (Bn * Tn)          // 8192
#define NHEADTOK (ROWS * Hn)    // 131072

// ---------------- fp32 scratch -------------------------------------------
#define SZ_X    ((size_t)ROWS * En)
#define OFF_X   ((size_t)0)
#define OFF_QT  (OFF_X + SZ_X)                      // fp32 GEMM outputs pre-LN
#define OFF_LG  (OFF_QT + SZ_X)                     // fallback logits scratch
#define OFF_RL  (OFF_LG + (size_t)ROWS * Vn)
#define TOTALF  (OFF_RL + ROWS + 64)
__device__ float g_buf[TOTALF];

// ---------------- fp16 scratch -------------------------------------------
#define HSZ_QKV ((size_t)NHEADTOK * Dh)             // 8,388,608
#define HOFF_XH ((size_t)0)                         // fp16 shadow of X
#define HOFF_Q  (HOFF_XH + SZ_X)
#define HOFF_K  (HOFF_Q + HSZ_QKV)
#define HOFF_V  (HOFF_K + HSZ_QKV)
#define HOFF_VT (HOFF_V + HSZ_QKV)
#define HOFF_O  (HOFF_VT + HSZ_QKV)
#define HOFF_FF (HOFF_O + HSZ_QKV)
#define HOFF_S  (HOFF_FF + (size_t)ROWS * FFn)      // scores -> probs (in place)
#define HOFF_WQ (HOFF_S + (size_t)Bn * Hn * Tn * Tn)
#define HOFF_WK (HOFF_WQ + (size_t)Ln * Dh * Dh)
#define HOFF_WV (HOFF_WK + (size_t)Ln * Dh * Dh)
#define HOFF_WO (HOFF_WV + (size_t)Ln * Dh * Dh)
#define HOFF_W1 (HOFF_WO + (size_t)Ln * En * En)
#define HOFF_W2 (HOFF_W1 + (size_t)Ln * FFn * En)
#define HOFF_LM (HOFF_W2 + (size_t)Ln * En * FFn)
#define TOTALH  (HOFF_LM + (size_t)Vn * En + 64)
__device__ __half g_hbuf[TOTALH];

__device__ int g_flags[2];

// =================== helpers (baseline PTX, proven R13) ===================
__device__ __forceinline__ uint32_t smem_u32(const void* p) {
    uint32_t a;
    asm("{ .reg .u64 t; cvta.to.shared.u64 t, %1; cvt.u32.u64 %0, t; }" : "=r"(a) : "l"(p));
    return a;
}
__device__ __forceinline__ void cp16(uint32_t dst, const void* src) {
    asm volatile("cp.async.ca.shared.global [%0], [%1], 16;" :: "r"(dst), "l"(src));
}
#define CP_COMMIT() asm volatile("cp.async.commit_group;" ::: "memory")
#define CP_WAIT0()  asm volatile("cp.async.wait_group 0;" ::: "memory")

__device__ __forceinline__ void mma16(float c[4], const uint32_t a[4], const uint32_t b[2]) {
    asm volatile(
        "mma.sync.aligned.m16n8k16.row.col.f32.f16.f16.f32 "
        "{%0,%1,%2,%3}, {%4,%5,%6,%7}, {%8,%9}, {%0,%1,%2,%3};"
        : "+f"(c[0]), "+f"(c[1]), "+f"(c[2]), "+f"(c[3])
        : "r"(a[0]), "r"(a[1]), "r"(a[2]), "r"(a[3]), "r"(b[0]), "r"(b[1]));
}

// =================== warp-mma fp16 NT GEMM (all-pure cp.async) ============
// C[M,N] = alpha*(A[M,K] @ B[N,K]^T) + bias, optional exact GELU.
// A and B are fp16 in gmem. BM=128, BN in {64,128}, BK=32, 8 warps (4x2).
// CAUSAL: 0 none, 1 skip tiles n0>m0 (scores), 2 cap K at m0+128 (A*V).
// COUT: 1 = fp16 output, 0 = fp32 output.
template<int BN, int CAUSAL, int COUT>
__global__ void __launch_bounds__(256)
mma_h(const __half* __restrict__ A, const __half* __restrict__ B,
      const float* __restrict__ bias, void* __restrict__ Cv,
      int K, int lda, int ldb, int ldc,
      int z2dim,
      long long sA1, long long sA2, long long sB1, long long sB2,
      long long sC1, long long sC2,
      float alpha, int fuse_gelu)
{
    constexpr int BM = 128, BK = 32, SPH = 40;      // padded stride (halves)
    constexpr int WN = BN / 2;                      // warp n-extent (4x2 warps)
    constexpr int NT = WN / 8;                      // n8 tiles per warp
    constexpr int NBC = BN / 64;                    // B 16B chunks per thread

    const int m0 = blockIdx.x * BM;
    const int n0 = blockIdx.y * BN;
    if (CAUSAL == 1 && n0 > m0) return;

    long long offC;
    {
        int bz = blockIdx.z;
        int z1 = bz / z2dim, z2 = bz - z1 * z2dim;
        A += z1 * sA1 + z2 * sA2;
        B += z1 * sB1 + z2 * sB2;
        offC = z1 * sC1 + z2 * sC2;
    }
    const int Keff = (CAUSAL == 2) ? min(K, m0 + BM) : K;

    extern __shared__ __half smh[];
    const uint32_t sbase = smem_u32(smh);
    __half* As0 = smh;                              // [2][BM*SPH]
    __half* Bs0 = smh + 2 * BM * SPH;               // [2][BN*SPH]

    const int tid = threadIdx.x;
    const int wid = tid >> 5, lane = tid & 31;
    const int wm = wid & 3, wn = wid >> 2;
    const int grp = lane >> 2, tig = lane & 3;

    float acc[2][NT][4];
#pragma unroll
    for (int mt = 0; mt < 2; mt++)
#pragma unroll
        for (int nt = 0; nt < NT; nt++)
#pragma unroll
            for (int j = 0; j < 4; j++) acc[mt][nt][j] = 0.f;

    auto cpA = [&](int kt, int s) {
        const int k0 = kt * BK;
        const uint32_t abase = sbase + (uint32_t)(s * BM * SPH) * 2;
#pragma unroll
        for (int i = 0; i < 2; i++) {               // 128 rows x 4 chunks of 8 halves
            int f = tid + i * 256;
            int r = f >> 2, c = f & 3;
            cp16(abase + (uint32_t)(r * SPH + c * 8) * 2,
                 A + (long long)(m0 + r) * lda + k0 + c * 8);
        }
    };
    auto cpB = [&](int kt, int s) {
        const int k0 = kt * BK;
        const uint32_t bbase = sbase + (uint32_t)((2 * BM + s * BN) * SPH) * 2;
#pragma unroll
        for (int i = 0; i < NBC; i++) {
            int f = tid + i * 256;
            int r = f >> 2, c = f & 3;
            cp16(bbase + (uint32_t)(r * SPH + c * 8) * 2,
                 B + (long long)(n0 + r) * ldb + k0 + c * 8);
        }
    };
    auto compute = [&](int s) {
        const __half* As = As0 + s * BM * SPH;
        const __half* Bs = Bs0 + s * BN * SPH;
#pragma unroll
        for (int ks = 0; ks < 2; ks++) {            // two k16 steps per BK=32
            const int kb = ks * 16;
            uint32_t af[2][4];
#pragma unroll
            for (int mt = 0; mt < 2; mt++) {
                int row = wm * 32 + mt * 16;
                af[mt][0] = *(const uint32_t*)&As[(row + grp) * SPH + kb + 2 * tig];
                af[mt][1] = *(const uint32_t*)&As[(row + grp + 8) * SPH + kb + 2 * tig];
                af[mt][2] = *(const uint32_t*)&As[(row + grp) * SPH + kb + 2 * tig + 8];
                af[mt][3] = *(const uint32_t*)&As[(row + grp + 8) * SPH + kb + 2 * tig + 8];
            }
            uint32_t bf[NT][2];
#pragma unroll
            for (int nt = 0; nt < NT; nt++) {
                int col = wn * WN + nt * 8 + grp;
                bf[nt][0] = *(const uint32_t*)&Bs[col * SPH + kb + 2 * tig];
                bf[nt][1] = *(const uint32_t*)&Bs[col * SPH + kb + 2 * tig + 8];
            }
#pragma unroll
            for (int mt = 0; mt < 2; mt++)
#pragma unroll
                for (int nt = 0; nt < NT; nt++)
                    mma16(acc[mt][nt], af[mt], bf[nt]);
        }
    };

    const int nkt = Keff / BK;
    cpA(0, 0);
    cpB(0, 0);
    CP_COMMIT();
    CP_WAIT0();
    __syncthreads();

    for (int kt = 0; kt < nkt; kt++) {
        const int s = kt & 1;
        if (kt + 1 < nkt) {
            cpA(kt + 1, s ^ 1);
            cpB(kt + 1, s ^ 1);
            CP_COMMIT();
        }
        compute(s);
        if (kt + 1 < nkt) {
            CP_WAIT0();
            __syncthreads();
        }
    }

    // ---- epilogue ----
#pragma unroll
    for (int mt = 0; mt < 2; mt++) {
#pragma unroll
        for (int nt = 0; nt < NT; nt++) {
            const int col = n0 + wn * WN + nt * 8 + tig * 2;
            float b0 = bias ? bias[col] : 0.f;
            float b1 = bias ? bias[col + 1] : 0.f;
#pragma unroll
            for (int h = 0; h < 2; h++) {
                const long long row = m0 + wm * 32 + mt * 16 + grp + h * 8;
                float v0 = acc[mt][nt][h * 2 + 0] * alpha + b0;
                float v1 = acc[mt][nt][h * 2 + 1] * alpha + b1;
                if (fuse_gelu) {
                    v0 = 0.5f * v0 * (1.0f + erff(v0 * 0.70710678118654752f));
                    v1 = 0.5f * v1 * (1.0f + erff(v1 * 0.70710678118654752f));
                }
                if (COUT) {
                    __half2 hv = __floats2half2_rn(v0, v1);
                    *(__half2*)((__half*)Cv + offC + row * ldc + col) = hv;
                } else {
                    *(float2*)((float*)Cv + offC + row * ldc + col) = make_float2(v0, v1);
                }
            }
        }
    }
}

#define SMEM_H(BN) (2 * (128 + (BN)) * 40 * 2)

// =================== small kernels ========================================
__global__ void h_copy(const float* __restrict__ s, __half* __restrict__ d,
                       long long n) {
    for (long long i = blockIdx.x * (long long)blockDim.x + threadIdx.x;
         i < n; i += (long long)gridDim.x * blockDim.x)
        d[i] = __float2half_rn(s[i]);
}

__global__ void detect_kernel(const void* idxp) {
    __shared__ int bad;
    if (threadIdx.x == 0) bad = 0;
    __syncthreads();
    const long long* p = (const long long*)idxp;
    for (int i = threadIdx.x; i < ROWS / 2; i += blockDim.x) {
        long long v = p[i];
        if (v < 0 || v >= Vn) bad = 1;
    }
    __syncthreads();
    if (threadIdx.x == 0) g_flags[0] = bad ? 0 : 1;
}

__device__ __forceinline__ long long read_token(const void* p, int i) {
    if (g_flags[0]) return ((const long long*)p)[i];
    return (long long)((const int*)p)[i];
}

__global__ void embed_kernel(const void* idxp, const float* __restrict__ tok,
                             const float* __restrict__ pos, float* __restrict__ x,
                             __half* __restrict__ xh) {
    int row = blockIdx.x;
    int t = row % Tn;
    long long token = read_token(idxp, row);
    const float* te = tok + (size_t)token * En;
    const float* pe = pos + (size_t)t * En;
    float* xo = x + (size_t)row * En;
    __half* ho = xh + (size_t)row * En;
#pragma unroll
    for (int i = 0; i < En / 256; i++) {
        int c = threadIdx.x + i * 256;
        float v = te[c] + pe[c];
        xo[c] = v;
        ho[c] = __float2half_rn(v);
    }
}

// V [B,T,H,Dh] fp16 -> Vt [B,H,Dh,T] fp16
__global__ void transpose_v(const __half* __restrict__ V, __half* __restrict__ Vt) {
    __shared__ __half tile[32][33];
    int bh = blockIdx.z;
    int b = bh / Hn, h = bh - b * Hn;
    int t0 = blockIdx.x * 32, d0 = blockIdx.y * 32;
    int tx = threadIdx.x, ty0 = threadIdx.y;
#pragma unroll
    for (int i = 0; i < 4; i++) {
        int ty = ty0 + i * 8;
        tile[ty][tx] = V[((size_t)(b * Tn + t0 + ty) * Hn + h) * Dh + d0 + tx];
    }
    __syncthreads();
#pragma unroll
    for (int i = 0; i < 4; i++) {
        int ty = ty0 + i * 8;
        Vt[((size_t)(b * Hn + h) * Dh + d0 + ty) * Tn + t0 + tx] = tile[tx][ty];
    }
}

// causal softmax over fp16 scores, in place (scores -> probs)
__global__ void softmax_causal(__half* __restrict__ S) {
    long long row = blockIdx.x;
    int i = (int)(row % Tn);
    __half* p = S + row * (long long)Tn;
    int n = i + 1;
    int jend = (i & ~127) + 128;         // A*V never reads past this row-tile's K cap
    int tid = threadIdx.x;
    __shared__ float red[256];

    float mx = -1e30f;
    for (int j = tid; j < n; j += 256) mx = fmaxf(mx, __half2float(p[j]));
    red[tid] = mx; __syncthreads();
    for (int s = 128; s > 0; s >>= 1) { if (tid < s) red[tid] = fmaxf(red[tid], red[tid + s]); __syncthreads(); }
    mx = red[0]; __syncthreads();

    float sum = 0.f;
    for (int j = tid; j < n; j += 256) sum += expf(__half2float(p[j]) - mx);
    red[tid] = sum; __syncthreads();
    for (int s = 128; s > 0; s >>= 1) { if (tid < s) red[tid] += red[tid + s]; __syncthreads(); }
    float inv = 1.0f / red[0];

    for (int j = tid; j < n; j += 256)
        p[j] = __float2half_rn(expf(__half2float(p[j]) - mx) * inv);
    for (int j = n + tid; j < jend; j += 256) p[j] = __float2half_rn(0.f);
}

// (a [+res]) -> LayerNorm, writes fp32 out and fp16 shadow
__global__ void add_layernorm(const float* __restrict__ a, const float* __restrict__ res,
                              const float* __restrict__ g, const float* __restrict__ b,
                              float* __restrict__ out, __half* __restrict__ outh)
{
    int row = blockIdx.x;
    const float* pa = a + (size_t)row * En;
    const float* pr = res ? res + (size_t)row * En : nullptr;
    float* po = out + (size_t)row * En;
    __half* ph = outh + (size_t)row * En;
    int tid = threadIdx.x;
    __shared__ float red[256];
    float v[En / 256];

    float s = 0.f;
#pragma unroll
    for (int i = 0; i < En / 256; i++) {
        int c = tid + i * 256;
        float x = pa[c] + (pr ? pr[c] : 0.f);
        v[i] = x; s += x;
    }
    red[tid] = s; __syncthreads();
    for (int st = 128; st > 0; st >>= 1) { if (tid < st) red[tid] += red[tid + st]; __syncthreads(); }
    float mean = red[0] * (1.0f / En); __syncthreads();

    float s2 = 0.f;
#pragma unroll
    for (int i = 0; i < En / 256; i++) { float d = v[i] - mean; s2 += d * d; }
    red[tid] = s2; __syncthreads();
    for (int st = 128; st > 0; st >>= 1) { if (tid < st) red[tid] += red[tid + st]; __syncthreads(); }
    float inv = rsqrtf(red[0] * (1.0f / En) + 1e-5f);

#pragma unroll
    for (int i = 0; i < En / 256; i++) {
        int c = tid + i * 256;
        float o = (v[i] - mean) * inv * g[c] + b[c];
        po[c] = o;
        ph[c] = __float2half_rn(o);
    }
}

// single-pass online logsumexp loss per row
__global__ void loss_rows(const float* __restrict__ logits, const void* tgt,
                          float* __restrict__ rowloss)
{
    int r = blockIdx.x;
    const float* p = logits + (size_t)r * Vn;
    int tid = threadIdx.x;
    __shared__ float rm[256], rs[256];

    float m = -1e30f, s = 0.f;
    for (int j = tid; j < Vn; j += 256) {
        float x = p[j];
        if (x > m) { s = s * expf(m - x) + 1.f; m = x; }
        else s += expf(x - m);
    }
    rm[tid] = m; rs[tid] = s; __syncthreads();
    for (int st = 128; st > 0; st >>= 1) {
        if (tid < st) {
            float m2 = rm[tid + st], s2 = rs[tid + st];
            float M = fmaxf(rm[tid], m2);
            rs[tid] = rs[tid] * expf(rm[tid] - M) + s2 * expf(m2 - M);
            rm[tid] = M;
        }
        __syncthreads();
    }
    if (tid == 0) {
        long long t = read_token(tgt, r);
        rowloss[r] = logf(rs[0]) + rm[0] - p[t];
    }
}

__global__ void loss_reduce(const float* __restrict__ rowloss, float* __restrict__ out) {
    __shared__ float red[256];
    int tid = threadIdx.x;
    float s = 0.f;
    for (int i = tid; i < ROWS; i += 256) s += rowloss[i];
    red[tid] = s; __syncthreads();
    for (int st = 128; st > 0; st >>= 1) { if (tid < st) red[tid] += red[tid + st]; __syncthreads(); }
    if (tid == 0) out[0] = red[0] * (1.0f / ROWS);
}

// =================== host orchestration ===================================
extern "C" void kernel_launch(void* const* d_in, const int* in_sizes, int n_in,
                              void* d_out, int out_size)
{
    const void*  idx     = d_in[0];
    const void*  tgt     = d_in[1];
    const float* tok_emb = (const float*)d_in[2];
    const float* pos_emb = (const float*)d_in[3];
    const float* Wq      = (const float*)d_in[4];
    const float* Wk      = (const float*)d_in[5];
    const float* Wv      = (const float*)d_in[6];
    const float* Wo      = (const float*)d_in[7];
    const float* bo      = (const float*)d_in[8];
    const float* ln1_g   = (const float*)d_in[9];
    const float* ln1_b   = (const float*)d_in[10];
    const float* W1      = (const float*)d_in[11];
    const float* b1      = (const float*)d_in[12];
    const float* W2      = (const float*)d_in[13];
    const float* b2      = (const float*)d_in[14];
    const float* ln2_g   = (const float*)d_in[15];
    const float* ln2_b   = (const float*)d_in[16];
    const float* lnf_g   = (const float*)d_in[17];
    const float* lnf_b   = (const float*)d_in[18];
    const float* lm_w    = (const float*)d_in[19];
    const float* lm_b    = (const float*)d_in[20];

    cudaFuncSetAttribute(mma_h<64, 0, 1>,  cudaFuncAttributeMaxDynamicSharedMemorySize, SMEM_H(64));
    cudaFuncSetAttribute(mma_h<128, 1, 1>, cudaFuncAttributeMaxDynamicSharedMemorySize, SMEM_H(128));
    cudaFuncSetAttribute(mma_h<64, 2, 1>,  cudaFuncAttributeMaxDynamicSharedMemorySize, SMEM_H(64));
    cudaFuncSetAttribute(mma_h<128, 0, 0>, cudaFuncAttributeMaxDynamicSharedMemorySize, SMEM_H(128));
    cudaFuncSetAttribute(mma_h<128, 0, 1>, cudaFuncAttributeMaxDynamicSharedMemorySize, SMEM_H(128));

    float* buf = nullptr;
    cudaGetSymbolAddress((void**)&buf, g_buf);
    __half* hb = nullptr;
    cudaGetSymbolAddress((void**)&hb, g_hbuf);

    float* X  = buf + OFF_X;
    float* QT = buf + OFF_QT;
    float* LG = buf + OFF_LG;
    float* RL = buf + OFF_RL;

    __half* Xh  = hb + HOFF_XH;
    __half* Qh  = hb + HOFF_Q;
    __half* Kh  = hb + HOFF_K;
    __half* Vh  = hb + HOFF_V;
    __half* Vth = hb + HOFF_VT;
    __half* Oh  = hb + HOFF_O;
    __half* FFh = hb + HOFF_FF;
    __half* Sh  = hb + HOFF_S;
    __half* WQh = hb + HOFF_WQ;
    __half* WKh = hb + HOFF_WK;
    __half* WVh = hb + HOFF_WV;
    __half* WOh = hb + HOFF_WO;
    __half* W1h = hb + HOFF_W1;
    __half* W2h = hb + HOFF_W2;
    __half* LMh = hb + HOFF_LM;

    const size_t NLOG = (size_t)ROWS * Vn;
    float* logits;
    long long loss_idx;
    if ((size_t)out_size >= NLOG + 1) { logits = (float*)d_out; loss_idx = (long long)NLOG; }
    else if ((size_t)out_size == NLOG) { logits = (float*)d_out; loss_idx = -1; }
    else { logits = LG; loss_idx = 0; }

    detect_kernel<<<1, 256>>>(idx);
    embed_kernel<<<ROWS, 256>>>(idx, tok_emb, pos_emb, X, Xh);

    // pre-convert all weights to fp16
    h_copy<<<64, 256>>>(Wq, WQh, (long long)Ln * Dh * Dh);
    h_copy<<<64, 256>>>(Wk, WKh, (long long)Ln * Dh * Dh);
    h_copy<<<64, 256>>>(Wv, WVh, (long long)Ln * Dh * Dh);
    h_copy<<<512, 256>>>(Wo, WOh, (long long)Ln * En * En);
    h_copy<<<512, 256>>>(W1, W1h, (long long)Ln * FFn * En);
    h_copy<<<512, 256>>>(W2, W2h, (long long)Ln * En * FFn);
    h_copy<<<512, 256>>>(lm_w, LMh, (long long)Vn * En);

    const long long TnE  = (long long)Tn * En;
    const long long TnTn = (long long)Tn * Tn;

    for (int l = 0; l < Ln; l++) {
        const __half* wq = WQh + (size_t)l * Dh * Dh;
        const __half* wk = WKh + (size_t)l * Dh * Dh;
        const __half* wv = WVh + (size_t)l * Dh * Dh;
        const __half* wo = WOh + (size_t)l * En * En;
        const __half* w1 = W1h + (size_t)l * FFn * En;
        const __half* w2 = W2h + (size_t)l * En * FFn;

        // q/k/v : A = Xh (pure), fp16 out
        dim3 gp(NHEADTOK / 128, 1, 1);
        mma_h<64, 0, 1><<<gp, 256, SMEM_H(64)>>>(Xh, wq, nullptr, Qh, Dh, Dh, Dh, Dh,
                                                 1, 0, 0, 0, 0, 0, 0, 1.0f, 0);
        mma_h<64, 0, 1><<<gp, 256, SMEM_H(64)>>>(Xh, wk, nullptr, Kh, Dh, Dh, Dh, Dh,
                                                 1, 0, 0, 0, 0, 0, 0, 1.0f, 0);
        mma_h<64, 0, 1><<<gp, 256, SMEM_H(64)>>>(Xh, wv, nullptr, Vh, Dh, Dh, Dh, Dh,
                                                 1, 0, 0, 0, 0, 0, 0, 1.0f, 0);
        transpose_v<<<dim3(Tn / 32, 2, Bn * Hn), dim3(32, 8)>>>(Vh, Vth);

        // scores = Q K^T / 8 : fp16 out into Sh (lower+diag tiles only)
        mma_h<128, 1, 1><<<dim3(Tn / 128, Tn / 128, Bn * Hn), 256, SMEM_H(128)>>>(
            Qh, Kh, nullptr, Sh, Dh, En, En, Tn,
            Hn, TnE, (long long)Dh, TnE, (long long)Dh,
            (long long)Hn * TnTn, TnTn, 0.125f, 0);

        softmax_causal<<<Bn * Hn * Tn, 256>>>(Sh);   // in place: scores -> probs

        // O = P @ Vt^T : fp16 out, K capped causally
        mma_h<64, 2, 1><<<dim3(Tn / 128, 1, Bn * Hn), 256, SMEM_H(64)>>>(
            Sh, Vth, nullptr, Oh, Tn, Tn, Tn, En,
            Hn, (long long)Hn * TnTn, TnTn,
            (long long)Hn * Dh * Tn, (long long)Dh * Tn,
            TnE, (long long)Dh, 1.0f, 0);

        // attn proj : fp32 out (feeds LN)
        mma_h<128, 0, 0><<<dim3(ROWS / 128, En / 128, 1), 256, SMEM_H(128)>>>(
            Oh, wo, bo + (size_t)l * En, QT, En, En, En, En,
            1, 0, 0, 0, 0, 0, 0, 1.0f, 0);
        add_layernorm<<<ROWS, 256>>>(QT, X, ln1_g + (size_t)l * En, ln1_b + (size_t)l * En, X, Xh);

        // FFN1 : A = Xh (pure), GELU, fp16 out
        mma_h<128, 0, 1><<<dim3(ROWS / 128, FFn / 128, 1), 256, SMEM_H(128)>>>(
            Xh, w1, b1 + (size_t)l * FFn, FFh, En, En, En, FFn,
            1, 0, 0, 0, 0, 0, 0, 1.0f, 1);
        // FFN2 : fp32 out
        mma_h<128, 0, 0><<<dim3(ROWS / 128, En / 128, 1), 256, SMEM_H(128)>>>(
            FFh, w2, b2 + (size_t)l * En, QT, FFn, FFn, FFn, En,
            1, 0, 0, 0, 0, 0, 0, 1.0f, 0);
        add_layernorm<<<ROWS, 256>>>(QT, X, ln2_g + (size_t)l * En, ln2_b + (size_t)l * En, X, Xh);
    }

    add_layernorm<<<ROWS, 256>>>(X, nullptr, lnf_g, lnf_b, X, Xh);

    // LM head : A = Xh (pure), fp32 logits
    mma_h<128, 0, 0><<<dim3(ROWS / 128, Vn / 128, 1), 256, SMEM_H(128)>>>(
        Xh, LMh, lm_b, logits, En, En, En, Vn,
        1, 0, 0, 0, 0, 0, 0, 1.0f, 0);

    loss_rows<<<ROWS, 256>>>(logits, tgt, RL);
    if (loss_idx >= 0)
        loss_reduce<<<1, 256>>>(RL, ((float*)d_out) + loss_idx);
}